// round 4
// baseline (speedup 1.0000x reference)
#include <cuda_runtime.h>
#include <math.h>
#include <stdint.h>

#define BQ    16
#define SEQ   512
#define NFch  32
#define ECH   128
#define HID   512
#define PRED  96
#define NFFT  64
#define HOPL  32
#define TOPM  32
#define WN    17
#define FB    33
#define LAMB  0.01f

#define ROWS  (BQ*NFch)      // 512  (b*32+n)
#define KTOT  (SEQ*ECH)      // 65536
#define KSPLIT 32
#define KCHUNK (KTOT/KSPLIT) // 2048

// ---------------- scratch (static device globals; no runtime alloc) --------
__device__ float2 g_c[ROWS*WN*TOPM];          // topk STFT values per (row,w,m)
__device__ int    g_fidx[ROWS*WN*TOPM];       // their frequency bins
__device__ float  g_v[6*WN*ECH];              // emb-contracted weight vectors
__device__ float  g_xo[(size_t)ROWS*KTOT];    // fused output (B,N,T,E) ~134MB
__device__ float  g_Hpart[(size_t)KSPLIT*ROWS*HID]; // split-K partials
__device__ float  g_H[ROWS*HID];              // reduced FC1 pre-activation

#define TWO_PI 6.28318530717958647692f
#define TWO_PI_D 6.28318530717958647692528676655900577

__device__ __forceinline__ int reflect_t(int j) {
    int t = j - 32;
    if (t < 0) t = -t;
    else if (t > SEQ-1) t = 2*(SEQ-1) - t;   // 1022 - t
    return t;
}

// ---------------- Kernel A: STFT (fp64-exact, f32-rounded) + top-32 --------
// Rank ORDER of the top-k matters downstream (xl/xr pairing), so the spectrum
// must match cuFFT's fp32 output as closely as possible: fp64 accumulation
// with exact twiddles, f32 frame products, correctly-rounded magnitudes.
__global__ void k_stft(const float* __restrict__ x) {
    __shared__ float  s_s[SEQ];
    __shared__ float  win_s[NFFT];
    __shared__ double cosd[NFFT], sind[NFFT];
    __shared__ float  Sre[WN*FB], Sim[WN*FB], Sab[WN*FB];
    int blk = blockIdx.x;           // b*32+n
    int b = blk >> 5, n = blk & 31;
    int tid = threadIdx.x;          // 128

    for (int t = tid; t < SEQ; t += 128) s_s[t] = x[(b*SEQ + t)*NFch + n];
    for (int t = tid; t < NFFT; t += 128) {
        float a = TWO_PI * (float)t / (float)NFFT;          // f32 arg, like reference
        win_s[t] = 0.5f - 0.5f * (float)cos((double)a);     // correctly-rounded cos
        double ad = TWO_PI_D * (double)t / 64.0;
        cosd[t] = cos(ad); sind[t] = sin(ad);
    }
    __syncthreads();

    for (int task = tid; task < WN*FB; task += 128) {
        int w = task / FB, f = task % FB;
        double re = 0.0, im = 0.0;
        for (int k = 0; k < NFFT; k++) {
            float v = s_s[reflect_t(w*HOPL + k)] * win_s[k];   // f32 like 'frames'
            int a = (f*k) & 63;                                 // exact angle index
            re = fma((double)v,  cosd[a], re);
            im = fma((double)v, -sind[a], im);
        }
        float rf = (float)re, imf = (float)im;
        Sre[task] = rf; Sim[task] = imf;
        Sab[task] = (float)sqrt((double)rf*rf + (double)imf*imf); // ~hypotf
    }
    __syncthreads();

    if (tid < WN) {
        int w = tid;
        float mag[FB]; bool used[FB];
        for (int f = 0; f < FB; f++) { mag[f] = Sab[w*FB+f]; used[f] = false; }
        int base = (blk*WN + w) * TOPM;
        for (int m = 0; m < TOPM; m++) {
            int best = 0; float bv = -1.f;
            for (int f = 0; f < FB; f++)
                if (!used[f] && mag[f] > bv) { bv = mag[f]; best = f; }  // stable: ties -> lower f
            used[best] = true;
            g_fidx[base+m] = best;
            g_c[base+m] = make_float2(Sre[w*FB+best], Sim[w*FB+best]);
        }
    }
}

// ---------------- Kernel B: v[k][w][f] = sum_e emb[e]*Wk[w,e,f] ------------
__global__ void k_vred(const float* __restrict__ emb,
                       const float* __restrict__ Wr,  const float* __restrict__ Wi,
                       const float* __restrict__ Wrl, const float* __restrict__ Wil,
                       const float* __restrict__ Wrr, const float* __restrict__ Wir) {
    int k = blockIdx.x / WN, w = blockIdx.x % WN;
    const float* Wm = (k==0)?Wr:(k==1)?Wi:(k==2)?Wrl:(k==3)?Wil:(k==4)?Wrr:Wir;
    int f = threadIdx.x;
    const float* base = Wm + (size_t)w*ECH*ECH + f;
    float acc = 0.f;
    #pragma unroll 4
    for (int e = 0; e < ECH; e++) acc = fmaf(emb[e], base[(size_t)e*ECH], acc);
    g_v[(k*WN + w)*ECH + f] = acc;
}

// ---------------- Kernel C: fused Y + scatter + irfft + OLA + bias ---------
#define SMEM_MAIN 94976
__global__ void k_main(const float* __restrict__ x, const float* __restrict__ emb,
                       const float* __restrict__ br, const float* __restrict__ bi) {
    extern __shared__ char smraw[];
    float2* tab     = (float2*)(smraw);
    float*  full_re = (float*) (smraw + 16896);
    float*  full_im = (float*) (smraw + 33792);
    float*  ring    = (float*) (smraw + 50688);
    float2* cc      = (float2*)(smraw + 83456);
    float*  vs      = (float*) (smraw + 87808);
    float*  win_s   = (float*) (smraw + 91904);
    float*  ienv    = (float*) (smraw + 92160);
    float*  emb_s   = (float*) (smraw + 92288);
    int*    fidx_s  = (int*)   (smraw + 92800);

    int tid = threadIdx.x;          // 256
    int blk = blockIdx.x;           // b*32+n
    int b = blk >> 5, n = blk & 31;

    for (int i = tid; i < FB*NFFT; i += 256) {
        int f = i >> 6, t = i & 63;
        double ad = TWO_PI_D * (double)((f*t) & 63) / 64.0;
        tab[i] = make_float2((float)cos(ad), (float)sin(ad));
    }
    for (int i = tid; i < NFFT; i += 256) {
        float a = TWO_PI * (float)i / (float)NFFT;
        win_s[i] = 0.5f - 0.5f * (float)cos((double)a);
    }
    for (int i = tid; i < HOPL; i += 256) {
        float a = TWO_PI * (float)i / (float)NFFT;
        float c = (float)cos((double)a);
        float w0 = 0.5f - 0.5f*c, w1 = 0.5f + 0.5f*c;
        ienv[i] = 1.0f / (w0*w0 + w1*w1);
    }
    for (int i = tid; i < ECH; i += 256) emb_s[i] = emb[i];
    for (int i = tid; i < WN*TOPM; i += 256) {
        cc[i]     = g_c[blk*WN*TOPM + i];
        fidx_s[i] = g_fidx[blk*WN*TOPM + i];
    }
    __syncthreads();

    int e0 = (tid & 31) << 2;       // e-fast across the warp -> broadcasts on tab
    int t0 = (tid >> 5) << 3;

    for (int w = 0; w < WN; w++) {
        for (int i = tid; i < 6*ECH; i += 256) {
            int k = i >> 7, e = i & 127;
            vs[i] = g_v[(k*WN + w)*ECH + e];
        }
        for (int i = tid; i < ECH; i += 256) {
            vs[6*ECH + i] = br[w*ECH + i];
            vs[7*ECH + i] = bi[w*ECH + i];
        }
        for (int i = tid; i < ECH*FB; i += 256) { full_re[i] = 0.f; full_im[i] = 0.f; }
        __syncthreads();

        for (int i = tid; i < ECH*TOPM; i += 256) {
            int m = i >> 7, e = i & 127;
            float2 c0 = cc[w*TOPM + m];
            float2 cl = (w > 0)    ? cc[(w-1)*TOPM + m] : make_float2(0.f,0.f);
            float2 cr = (w < WN-1) ? cc[(w+1)*TOPM + m] : make_float2(0.f,0.f);
            float vr  = vs[e],        vi  = vs[ECH+e];
            float vrl = vs[2*ECH+e],  vil = vs[3*ECH+e];
            float vrr = vs[4*ECH+e],  vir = vs[5*ECH+e];
            float ore = c0.x*vr - c0.y*vi + cl.x*vrl - cl.y*vil + cr.x*vrr - cr.y*vir + vs[6*ECH+e];
            float oim = c0.y*vr + c0.x*vi + cl.y*vrl + cl.x*vil + cr.y*vrr + cr.x*vir + vs[7*ECH+e];
            float yre = fmaxf(fmaxf(ore, 0.f) - LAMB, 0.f);
            float yim = fmaxf(fmaxf(oim, 0.f) - LAMB, 0.f);
            int f = fidx_s[w*TOPM + m];
            if (f == 0 || f == FB-1) {
                full_re[f*ECH + e] = yre * 0.015625f;   // 1/64, imag ignored by irfft
                full_im[f*ECH + e] = 0.f;
            } else {
                full_re[f*ECH + e] = yre * 0.03125f;    // 2/64
                full_im[f*ECH + e] = yim * 0.03125f;
            }
        }
        __syncthreads();

        float acc[4][8];
        #pragma unroll
        for (int jj = 0; jj < 4; jj++)
            #pragma unroll
            for (int kk = 0; kk < 8; kk++) acc[jj][kk] = 0.f;

        for (int f = 0; f < FB; f++) {
            float4 yr = *(const float4*)&full_re[f*ECH + e0];
            float4 yi = *(const float4*)&full_im[f*ECH + e0];
            float yra[4] = {yr.x, yr.y, yr.z, yr.w};
            float yia[4] = {yi.x, yi.y, yi.z, yi.w};
            #pragma unroll
            for (int kk = 0; kk < 8; kk++) {
                float2 ct = tab[f*NFFT + t0 + kk];
                #pragma unroll
                for (int jj = 0; jj < 4; jj++)
                    acc[jj][kk] = fmaf(yra[jj], ct.x, fmaf(-yia[jj], ct.y, acc[jj][kk]));
            }
        }

        #pragma unroll
        for (int kk = 0; kk < 8; kk++) {
            int t = t0 + kk;
            int slot = (w*HOPL + t) & 63;
            float wm = win_s[t];
            float4* rp = (float4*)&ring[slot*ECH + e0];
            float4 v;
            v.x = acc[0][kk]*wm; v.y = acc[1][kk]*wm;
            v.z = acc[2][kk]*wm; v.w = acc[3][kk]*wm;
            if (t < HOPL && w > 0) {
                float4 o = *rp;
                v.x += o.x; v.y += o.y; v.z += o.z; v.w += o.w;
            }
            *rp = v;
        }
        __syncthreads();

        if (w > 0) {
            for (int i = tid; i < HOPL*ECH; i += 256) {
                int r = i >> 7, e = i & 127;
                int t_out = (w-1)*HOPL + r;
                int slot = (w*HOPL + r) & 63;
                float val = ring[slot*ECH + e] * ienv[r]
                          + x[(b*SEQ + t_out)*NFch + n] * emb_s[e];
                g_xo[(size_t)blk*KTOT + t_out*ECH + e] = val;
            }
        }
        __syncthreads();
    }
}

// ---------------- Kernel D: FC1 split-K SGEMM (exact fp32) -----------------
__global__ void k_fc1(const float* __restrict__ w1) {
    __shared__ float As[8][128];
    __shared__ float Bs[8][128];
    int m0 = blockIdx.x * 128, n0 = blockIdx.y * 128;
    int kbase = blockIdx.z * KCHUNK;
    int tid = threadIdx.x;          // 256
    int ty = tid >> 4, tx = tid & 15;
    float acc[8][8];
    #pragma unroll
    for (int i = 0; i < 8; i++)
        #pragma unroll
        for (int j = 0; j < 8; j++) acc[i][j] = 0.f;

    int arow = tid >> 1, aq = tid & 1;
    for (int kc = kbase; kc < kbase + KCHUNK; kc += 8) {
        float4 a4 = *(const float4*)&g_xo[(size_t)(m0+arow)*KTOT + kc + aq*4];
        As[aq*4+0][arow] = a4.x; As[aq*4+1][arow] = a4.y;
        As[aq*4+2][arow] = a4.z; As[aq*4+3][arow] = a4.w;
        #pragma unroll
        for (int it = 0; it < 4; it++) {
            int i = tid + it*256;
            int k = i >> 7, nn = i & 127;
            Bs[k][nn] = w1[(size_t)(kc+k)*HID + n0 + nn];
        }
        __syncthreads();
        #pragma unroll
        for (int kk = 0; kk < 8; kk++) {
            float a[8], bv[8];
            #pragma unroll
            for (int i = 0; i < 8; i++) a[i]  = As[kk][ty*8+i];
            #pragma unroll
            for (int j = 0; j < 8; j++) bv[j] = Bs[kk][tx*8+j];
            #pragma unroll
            for (int i = 0; i < 8; i++)
                #pragma unroll
                for (int j = 0; j < 8; j++)
                    acc[i][j] = fmaf(a[i], bv[j], acc[i][j]);
        }
        __syncthreads();
    }
    size_t base = (size_t)blockIdx.z * (ROWS*HID);
    #pragma unroll
    for (int i = 0; i < 8; i++)
        #pragma unroll
        for (int j = 0; j < 8; j++)
            g_Hpart[base + (size_t)(m0+ty*8+i)*HID + n0 + tx*8+j] = acc[i][j];
}

__global__ void k_hred() {
    int i = blockIdx.x * 256 + threadIdx.x;
    if (i >= ROWS*HID) return;
    float s = 0.f;
    #pragma unroll
    for (int z = 0; z < KSPLIT; z++) s += g_Hpart[(size_t)z*(ROWS*HID) + i];
    g_H[i] = s;
}

// ---------------- Kernel E: leaky_relu + FC2 + output transpose ------------
__global__ void k_fc2(const float* __restrict__ b1, const float* __restrict__ w2,
                      const float* __restrict__ b2, float* __restrict__ out) {
    __shared__ float hrow[HID];
    int row = blockIdx.x;           // b*32+n
    int tid = threadIdx.x;          // 96
    for (int i = tid; i < HID; i += PRED) {
        float v = g_H[row*HID + i] + b1[i];
        hrow[i] = v > 0.f ? v : 0.01f * v;
    }
    __syncthreads();
    int b = row >> 5, n = row & 31;
    float acc = b2[tid];
    #pragma unroll 4
    for (int h = 0; h < HID; h++) acc = fmaf(hrow[h], w2[h*PRED + tid], acc);
    out[(b*PRED + tid)*NFch + n] = acc;
}

// ---------------------------------------------------------------------------
extern "C" void kernel_launch(void* const* d_in, const int* in_sizes, int n_in,
                              void* d_out, int out_size) {
    const float* x   = (const float*)d_in[0];
    const float* emb = (const float*)d_in[1];
    const float* br  = (const float*)d_in[8];
    const float* bi  = (const float*)d_in[9];
    const float* w1  = (const float*)d_in[10];
    const float* b1  = (const float*)d_in[11];
    const float* w2  = (const float*)d_in[12];
    const float* b2  = (const float*)d_in[13];
    float* out = (float*)d_out;

    cudaFuncSetAttribute(k_main, cudaFuncAttributeMaxDynamicSharedMemorySize, SMEM_MAIN);

    k_stft<<<ROWS, 128>>>(x);
    k_vred<<<6*WN, 128>>>(emb, (const float*)d_in[2], (const float*)d_in[3],
                          (const float*)d_in[4], (const float*)d_in[5],
                          (const float*)d_in[6], (const float*)d_in[7]);
    k_main<<<ROWS, 256, SMEM_MAIN>>>(x, emb, br, bi);
    k_fc1<<<dim3(4, 4, KSPLIT), 256>>>(w1);
    k_hred<<<(ROWS*HID + 255)/256, 256>>>();
    k_fc2<<<ROWS, PRED>>>(b1, w2, b2, out);
}

// round 5
// speedup vs baseline: 2.0114x; 2.0114x over previous
#include <cuda_runtime.h>
#include <math.h>
#include <stdint.h>

#define BQ    16
#define SEQ   512
#define NFch  32
#define ECH   128
#define HID   512
#define PRED  96
#define NFFT  64
#define HOPL  32
#define TOPM  32
#define WN    17
#define FB    33
#define LAMB  0.01f

#define ROWS  (BQ*NFch)      // 512  (b*32+n)
#define KTOT  (SEQ*ECH)      // 65536
#define KSPLIT 32
#define KCHUNK (KTOT/KSPLIT) // 2048
#define BK    32

// ---------------- scratch (static device globals; no runtime alloc) --------
__device__ float2 g_c[ROWS*WN*TOPM];
__device__ int    g_fidx[ROWS*WN*TOPM];
__device__ float  g_v[6*WN*ECH];
__device__ float  g_xo[(size_t)ROWS*KTOT];          // ~134MB
__device__ float  g_Hpart[(size_t)KSPLIT*ROWS*HID];
__device__ float  g_H[ROWS*HID];

#define TWO_PI 6.28318530717958647692f
#define TWO_PI_D 6.28318530717958647692528676655900577

__device__ __forceinline__ int reflect_t(int j) {
    int t = j - 32;
    if (t < 0) t = -t;
    else if (t > SEQ-1) t = 2*(SEQ-1) - t;
    return t;
}

__device__ __forceinline__ uint32_t f2tf32u(float f) {
    uint32_t r; asm("cvt.rna.tf32.f32 %0, %1;" : "=r"(r) : "f"(f)); return r;
}

__device__ __forceinline__ void mma_tf32(float* c, const uint32_t* a, const uint32_t* b) {
    asm volatile("mma.sync.aligned.m16n8k8.row.col.f32.tf32.tf32.f32 "
        "{%0,%1,%2,%3}, {%4,%5,%6,%7}, {%8,%9}, {%0,%1,%2,%3};"
        : "+f"(c[0]), "+f"(c[1]), "+f"(c[2]), "+f"(c[3])
        : "r"(a[0]), "r"(a[1]), "r"(a[2]), "r"(a[3]), "r"(b[0]), "r"(b[1]));
}

// ---------------- Kernel A: STFT (fp64-exact, f32-rounded) + top-32 --------
__global__ void k_stft(const float* __restrict__ x) {
    __shared__ float  s_s[SEQ];
    __shared__ float  win_s[NFFT];
    __shared__ double cosd[NFFT], sind[NFFT];
    __shared__ float  Sre[WN*FB], Sim[WN*FB], Sab[WN*FB];
    int blk = blockIdx.x;
    int b = blk >> 5, n = blk & 31;
    int tid = threadIdx.x;          // 128

    for (int t = tid; t < SEQ; t += 128) s_s[t] = x[(b*SEQ + t)*NFch + n];
    for (int t = tid; t < NFFT; t += 128) {
        float a = TWO_PI * (float)t / (float)NFFT;
        win_s[t] = 0.5f - 0.5f * (float)cos((double)a);
        double ad = TWO_PI_D * (double)t / 64.0;
        cosd[t] = cos(ad); sind[t] = sin(ad);
    }
    __syncthreads();

    for (int task = tid; task < WN*FB; task += 128) {
        int w = task / FB, f = task % FB;
        double re = 0.0, im = 0.0;
        for (int k = 0; k < NFFT; k++) {
            float v = s_s[reflect_t(w*HOPL + k)] * win_s[k];
            int a = (f*k) & 63;
            re = fma((double)v,  cosd[a], re);
            im = fma((double)v, -sind[a], im);
        }
        float rf = (float)re, imf = (float)im;
        Sre[task] = rf; Sim[task] = imf;
        Sab[task] = (float)sqrt((double)rf*rf + (double)imf*imf);
    }
    __syncthreads();

    if (tid < WN) {
        int w = tid;
        float mag[FB]; bool used[FB];
        for (int f = 0; f < FB; f++) { mag[f] = Sab[w*FB+f]; used[f] = false; }
        int base = (blk*WN + w) * TOPM;
        for (int m = 0; m < TOPM; m++) {
            int best = 0; float bv = -1.f;
            for (int f = 0; f < FB; f++)
                if (!used[f] && mag[f] > bv) { bv = mag[f]; best = f; }
            used[best] = true;
            g_fidx[base+m] = best;
            g_c[base+m] = make_float2(Sre[w*FB+best], Sim[w*FB+best]);
        }
    }
}

// ---------------- Kernel B: v[k][w][f] = sum_e emb[e]*Wk[w,e,f] ------------
__global__ void k_vred(const float* __restrict__ emb,
                       const float* __restrict__ Wr,  const float* __restrict__ Wi,
                       const float* __restrict__ Wrl, const float* __restrict__ Wil,
                       const float* __restrict__ Wrr, const float* __restrict__ Wir) {
    int k = blockIdx.x / WN, w = blockIdx.x % WN;
    const float* Wm = (k==0)?Wr:(k==1)?Wi:(k==2)?Wrl:(k==3)?Wil:(k==4)?Wrr:Wir;
    int f = threadIdx.x;
    const float* base = Wm + (size_t)w*ECH*ECH + f;
    float acc = 0.f;
    #pragma unroll 4
    for (int e = 0; e < ECH; e++) acc = fmaf(emb[e], base[(size_t)e*ECH], acc);
    g_v[(k*WN + w)*ECH + f] = acc;
}

// ---------------- Kernel C: fused Y + scatter + irfft + OLA + bias ---------
#define SMEM_MAIN 94976
__global__ void k_main(const float* __restrict__ x, const float* __restrict__ emb,
                       const float* __restrict__ br, const float* __restrict__ bi) {
    extern __shared__ char smraw[];
    float2* tab     = (float2*)(smraw);
    float*  full_re = (float*) (smraw + 16896);
    float*  full_im = (float*) (smraw + 33792);
    float*  ring    = (float*) (smraw + 50688);
    float2* cc      = (float2*)(smraw + 83456);
    float*  vs      = (float*) (smraw + 87808);
    float*  win_s   = (float*) (smraw + 91904);
    float*  ienv    = (float*) (smraw + 92160);
    float*  emb_s   = (float*) (smraw + 92288);
    int*    fidx_s  = (int*)   (smraw + 92800);

    int tid = threadIdx.x;          // 256
    int blk = blockIdx.x;
    int b = blk >> 5, n = blk & 31;

    for (int i = tid; i < FB*NFFT; i += 256) {
        int f = i >> 6, t = i & 63;
        double ad = TWO_PI_D * (double)((f*t) & 63) / 64.0;
        tab[i] = make_float2((float)cos(ad), (float)sin(ad));
    }
    for (int i = tid; i < NFFT; i += 256) {
        float a = TWO_PI * (float)i / (float)NFFT;
        win_s[i] = 0.5f - 0.5f * (float)cos((double)a);
    }
    for (int i = tid; i < HOPL; i += 256) {
        float a = TWO_PI * (float)i / (float)NFFT;
        float c = (float)cos((double)a);
        float w0 = 0.5f - 0.5f*c, w1 = 0.5f + 0.5f*c;
        ienv[i] = 1.0f / (w0*w0 + w1*w1);
    }
    for (int i = tid; i < ECH; i += 256) emb_s[i] = emb[i];
    for (int i = tid; i < WN*TOPM; i += 256) {
        cc[i]     = g_c[blk*WN*TOPM + i];
        fidx_s[i] = g_fidx[blk*WN*TOPM + i];
    }
    __syncthreads();

    int e0 = (tid & 31) << 2;
    int t0 = (tid >> 5) << 3;

    for (int w = 0; w < WN; w++) {
        for (int i = tid; i < 6*ECH; i += 256) {
            int k = i >> 7, e = i & 127;
            vs[i] = g_v[(k*WN + w)*ECH + e];
        }
        for (int i = tid; i < ECH; i += 256) {
            vs[6*ECH + i] = br[w*ECH + i];
            vs[7*ECH + i] = bi[w*ECH + i];
        }
        for (int i = tid; i < ECH*FB; i += 256) { full_re[i] = 0.f; full_im[i] = 0.f; }
        __syncthreads();

        for (int i = tid; i < ECH*TOPM; i += 256) {
            int m = i >> 7, e = i & 127;
            float2 c0 = cc[w*TOPM + m];
            float2 cl = (w > 0)    ? cc[(w-1)*TOPM + m] : make_float2(0.f,0.f);
            float2 cr = (w < WN-1) ? cc[(w+1)*TOPM + m] : make_float2(0.f,0.f);
            float vr  = vs[e],        vi  = vs[ECH+e];
            float vrl = vs[2*ECH+e],  vil = vs[3*ECH+e];
            float vrr = vs[4*ECH+e],  vir = vs[5*ECH+e];
            float ore = c0.x*vr - c0.y*vi + cl.x*vrl - cl.y*vil + cr.x*vrr - cr.y*vir + vs[6*ECH+e];
            float oim = c0.y*vr + c0.x*vi + cl.y*vrl + cl.x*vil + cr.y*vrr + cr.x*vir + vs[7*ECH+e];
            float yre = fmaxf(fmaxf(ore, 0.f) - LAMB, 0.f);
            float yim = fmaxf(fmaxf(oim, 0.f) - LAMB, 0.f);
            int f = fidx_s[w*TOPM + m];
            if (f == 0 || f == FB-1) {
                full_re[f*ECH + e] = yre * 0.015625f;
                full_im[f*ECH + e] = 0.f;
            } else {
                full_re[f*ECH + e] = yre * 0.03125f;
                full_im[f*ECH + e] = yim * 0.03125f;
            }
        }
        __syncthreads();

        float acc[4][8];
        #pragma unroll
        for (int jj = 0; jj < 4; jj++)
            #pragma unroll
            for (int kk = 0; kk < 8; kk++) acc[jj][kk] = 0.f;

        for (int f = 0; f < FB; f++) {
            float4 yr = *(const float4*)&full_re[f*ECH + e0];
            float4 yi = *(const float4*)&full_im[f*ECH + e0];
            float yra[4] = {yr.x, yr.y, yr.z, yr.w};
            float yia[4] = {yi.x, yi.y, yi.z, yi.w};
            #pragma unroll
            for (int kk = 0; kk < 8; kk++) {
                float2 ct = tab[f*NFFT + t0 + kk];
                #pragma unroll
                for (int jj = 0; jj < 4; jj++)
                    acc[jj][kk] = fmaf(yra[jj], ct.x, fmaf(-yia[jj], ct.y, acc[jj][kk]));
            }
        }

        #pragma unroll
        for (int kk = 0; kk < 8; kk++) {
            int t = t0 + kk;
            int slot = (w*HOPL + t) & 63;
            float wm = win_s[t];
            float4* rp = (float4*)&ring[slot*ECH + e0];
            float4 v;
            v.x = acc[0][kk]*wm; v.y = acc[1][kk]*wm;
            v.z = acc[2][kk]*wm; v.w = acc[3][kk]*wm;
            if (t < HOPL && w > 0) {
                float4 o = *rp;
                v.x += o.x; v.y += o.y; v.z += o.z; v.w += o.w;
            }
            *rp = v;
        }
        __syncthreads();

        if (w > 0) {
            for (int i = tid; i < HOPL*ECH; i += 256) {
                int r = i >> 7, e = i & 127;
                int t_out = (w-1)*HOPL + r;
                int slot = (w*HOPL + r) & 63;
                float val = ring[slot*ECH + e] * ienv[r]
                          + x[(b*SEQ + t_out)*NFch + n] * emb_s[e];
                g_xo[(size_t)blk*KTOT + t_out*ECH + e] = val;
            }
        }
        __syncthreads();
    }
}

// ---------------- Kernel D: FC1 split-K, 3xTF32 tensor-core GEMM -----------
// Dynamic smem: Ah[128][36], Al[128][36], Bh[32][132], Bl[32][132]
#define SA 36
#define SB 132
#define SMEM_FC1 (2*128*SA*4 + 2*BK*SB*4)   // 36864 + 33792 = 70656
__global__ __launch_bounds__(256) void k_fc1(const float* __restrict__ w1) {
    extern __shared__ float sm[];
    float* Ah = sm;
    float* Al = Ah + 128*SA;
    float* Bh = Al + 128*SA;
    float* Bl = Bh + BK*SB;

    int m0 = blockIdx.x * 128, n0 = blockIdx.y * 128;
    int kbase = blockIdx.z * KCHUNK;
    int tid = threadIdx.x, lane = tid & 31, wid = tid >> 5;
    int wm = wid >> 1, wn = wid & 1;          // warp tile: 32(M) x 64(N)
    int ra = lane >> 2, ca = lane & 3;

    float acc[2][8][4];
    #pragma unroll
    for (int i = 0; i < 2; i++)
        #pragma unroll
        for (int j = 0; j < 8; j++)
            #pragma unroll
            for (int q = 0; q < 4; q++) acc[i][j][q] = 0.f;

    float4 pa[4], pb[4];
    // prologue load
    #pragma unroll
    for (int i = 0; i < 4; i++) {
        int l = tid + i*256;
        int m = l >> 3, kq = (l & 7) * 4;
        pa[i] = *(const float4*)&g_xo[(size_t)(m0+m)*KTOT + kbase + kq];
        int k = l >> 5, nq = (l & 31) * 4;
        pb[i] = *(const float4*)&w1[(size_t)(kbase+k)*HID + n0 + nq];
    }

    for (int it = 0; it < KCHUNK/BK; it++) {
        // split+store staged tiles
        #pragma unroll
        for (int i = 0; i < 4; i++) {
            int l = tid + i*256;
            int m = l >> 3, kq = (l & 7) * 4;
            float4 v = pa[i], h, lo;
            h.x = __uint_as_float(f2tf32u(v.x)); lo.x = __uint_as_float(f2tf32u(v.x - h.x));
            h.y = __uint_as_float(f2tf32u(v.y)); lo.y = __uint_as_float(f2tf32u(v.y - h.y));
            h.z = __uint_as_float(f2tf32u(v.z)); lo.z = __uint_as_float(f2tf32u(v.z - h.z));
            h.w = __uint_as_float(f2tf32u(v.w)); lo.w = __uint_as_float(f2tf32u(v.w - h.w));
            *(float4*)&Ah[m*SA + kq] = h; *(float4*)&Al[m*SA + kq] = lo;
            int k = l >> 5, nq = (l & 31) * 4;
            float4 w = pb[i], wh, wl;
            wh.x = __uint_as_float(f2tf32u(w.x)); wl.x = __uint_as_float(f2tf32u(w.x - wh.x));
            wh.y = __uint_as_float(f2tf32u(w.y)); wl.y = __uint_as_float(f2tf32u(w.y - wh.y));
            wh.z = __uint_as_float(f2tf32u(w.z)); wl.z = __uint_as_float(f2tf32u(w.z - wh.z));
            wh.w = __uint_as_float(f2tf32u(w.w)); wl.w = __uint_as_float(f2tf32u(w.w - wh.w));
            *(float4*)&Bh[k*SB + nq] = wh; *(float4*)&Bl[k*SB + nq] = wl;
        }
        __syncthreads();

        // prefetch next stage into registers (overlaps with compute)
        if (it + 1 < KCHUNK/BK) {
            int kc = kbase + (it+1)*BK;
            #pragma unroll
            for (int i = 0; i < 4; i++) {
                int l = tid + i*256;
                int m = l >> 3, kq = (l & 7) * 4;
                pa[i] = *(const float4*)&g_xo[(size_t)(m0+m)*KTOT + kc + kq];
                int k = l >> 5, nq = (l & 31) * 4;
                pb[i] = *(const float4*)&w1[(size_t)(kc+k)*HID + n0 + nq];
            }
        }

        #pragma unroll
        for (int ks = 0; ks < BK/8; ks++) {
            int k0 = ks*8 + ca;
            uint32_t ah[2][4], al[2][4];
            #pragma unroll
            for (int i = 0; i < 2; i++) {
                int mb = wm*32 + i*16;
                ah[i][0] = __float_as_uint(Ah[(mb+ra  )*SA + k0  ]);
                ah[i][1] = __float_as_uint(Ah[(mb+ra+8)*SA + k0  ]);
                ah[i][2] = __float_as_uint(Ah[(mb+ra  )*SA + k0+4]);
                ah[i][3] = __float_as_uint(Ah[(mb+ra+8)*SA + k0+4]);
                al[i][0] = __float_as_uint(Al[(mb+ra  )*SA + k0  ]);
                al[i][1] = __float_as_uint(Al[(mb+ra+8)*SA + k0  ]);
                al[i][2] = __float_as_uint(Al[(mb+ra  )*SA + k0+4]);
                al[i][3] = __float_as_uint(Al[(mb+ra+8)*SA + k0+4]);
            }
            #pragma unroll
            for (int j = 0; j < 8; j++) {
                int nb = wn*64 + j*8 + ra;
                uint32_t bh[2], bl[2];
                bh[0] = __float_as_uint(Bh[(k0  )*SB + nb]);
                bh[1] = __float_as_uint(Bh[(k0+4)*SB + nb]);
                bl[0] = __float_as_uint(Bl[(k0  )*SB + nb]);
                bl[1] = __float_as_uint(Bl[(k0+4)*SB + nb]);
                #pragma unroll
                for (int i = 0; i < 2; i++) {
                    mma_tf32(acc[i][j], al[i], bh);   // small terms first
                    mma_tf32(acc[i][j], ah[i], bl);
                    mma_tf32(acc[i][j], ah[i], bh);
                }
            }
        }
        __syncthreads();
    }

    // epilogue: write split-K partials (deterministic reduction in k_hred)
    size_t base = (size_t)blockIdx.z * (ROWS*HID);
    #pragma unroll
    for (int i = 0; i < 2; i++) {
        #pragma unroll
        for (int j = 0; j < 8; j++) {
            int row = m0 + wm*32 + i*16 + ra;
            int col = n0 + wn*64 + j*8 + ca*2;
            *(float2*)&g_Hpart[base + (size_t)row*HID + col]     = make_float2(acc[i][j][0], acc[i][j][1]);
            *(float2*)&g_Hpart[base + (size_t)(row+8)*HID + col] = make_float2(acc[i][j][2], acc[i][j][3]);
        }
    }
}

__global__ void k_hred() {
    int i = blockIdx.x * 256 + threadIdx.x;
    if (i >= ROWS*HID) return;
    float s = 0.f;
    #pragma unroll
    for (int z = 0; z < KSPLIT; z++) s += g_Hpart[(size_t)z*(ROWS*HID) + i];
    g_H[i] = s;
}

// ---------------- Kernel E: leaky_relu + FC2 + output transpose ------------
__global__ void k_fc2(const float* __restrict__ b1, const float* __restrict__ w2,
                      const float* __restrict__ b2, float* __restrict__ out) {
    __shared__ float hrow[HID];
    int row = blockIdx.x;
    int tid = threadIdx.x;          // 96
    for (int i = tid; i < HID; i += PRED) {
        float v = g_H[row*HID + i] + b1[i];
        hrow[i] = v > 0.f ? v : 0.01f * v;
    }
    __syncthreads();
    int b = row >> 5, n = row & 31;
    float acc = b2[tid];
    #pragma unroll 4
    for (int h = 0; h < HID; h++) acc = fmaf(hrow[h], w2[h*PRED + tid], acc);
    out[(b*PRED + tid)*NFch + n] = acc;
}

// ---------------------------------------------------------------------------
extern "C" void kernel_launch(void* const* d_in, const int* in_sizes, int n_in,
                              void* d_out, int out_size) {
    const float* x   = (const float*)d_in[0];
    const float* emb = (const float*)d_in[1];
    const float* br  = (const float*)d_in[8];
    const float* bi  = (const float*)d_in[9];
    const float* w1  = (const float*)d_in[10];
    const float* b1  = (const float*)d_in[11];
    const float* w2  = (const float*)d_in[12];
    const float* b2  = (const float*)d_in[13];
    float* out = (float*)d_out;

    cudaFuncSetAttribute(k_main, cudaFuncAttributeMaxDynamicSharedMemorySize, SMEM_MAIN);
    cudaFuncSetAttribute(k_fc1,  cudaFuncAttributeMaxDynamicSharedMemorySize, SMEM_FC1);

    k_stft<<<ROWS, 128>>>(x);
    k_vred<<<6*WN, 128>>>(emb, (const float*)d_in[2], (const float*)d_in[3],
                          (const float*)d_in[4], (const float*)d_in[5],
                          (const float*)d_in[6], (const float*)d_in[7]);
    k_main<<<ROWS, 256, SMEM_MAIN>>>(x, emb, br, bi);
    k_fc1<<<dim3(4, 4, KSPLIT), 256, SMEM_FC1>>>(w1);
    k_hred<<<(ROWS*HID + 255)/256, 256>>>();
    k_fc2<<<ROWS, PRED>>>(b1, w2, b2, out);
}

// round 6
// speedup vs baseline: 2.0154x; 1.0019x over previous
#include <cuda_runtime.h>
#include <math.h>
#include <stdint.h>

#define BQ    16
#define SEQ   512
#define NFch  32
#define ECH   128
#define HID   512
#define PRED  96
#define NFFT  64
#define HOPL  32
#define TOPM  32
#define WN    17
#define FB    33
#define LAMB  0.01f

#define ROWS  (BQ*NFch)      // 512  (b*32+n)
#define KTOT  (SEQ*ECH)      // 65536
#define KSPLIT 32
#define KCHUNK (KTOT/KSPLIT) // 2048
#define BK    32
#define NSTAGE (KCHUNK/BK)   // 64

// ---------------- scratch (static device globals; no runtime alloc) --------
__device__ float2 g_c[ROWS*WN*TOPM];
__device__ int    g_fidx[ROWS*WN*TOPM];
__device__ float  g_v[6*WN*ECH];
__device__ float  g_xo[(size_t)ROWS*KTOT];          // ~134MB
__device__ float  g_Hpart[(size_t)KSPLIT*ROWS*HID];
__device__ float  g_H[ROWS*HID];

#define TWO_PI 6.28318530717958647692f
#define TWO_PI_D 6.28318530717958647692528676655900577

__device__ __forceinline__ int reflect_t(int j) {
    int t = j - 32;
    if (t < 0) t = -t;
    else if (t > SEQ-1) t = 2*(SEQ-1) - t;
    return t;
}

__device__ __forceinline__ uint32_t f2tf32u(float f) {
    uint32_t r; asm("cvt.rna.tf32.f32 %0, %1;" : "=r"(r) : "f"(f)); return r;
}

__device__ __forceinline__ void mma_tf32(float* c, const uint32_t* a, const uint32_t* b) {
    asm volatile("mma.sync.aligned.m16n8k8.row.col.f32.tf32.tf32.f32 "
        "{%0,%1,%2,%3}, {%4,%5,%6,%7}, {%8,%9}, {%0,%1,%2,%3};"
        : "+f"(c[0]), "+f"(c[1]), "+f"(c[2]), "+f"(c[3])
        : "r"(a[0]), "r"(a[1]), "r"(a[2]), "r"(a[3]), "r"(b[0]), "r"(b[1]));
}

__device__ __forceinline__ uint32_t smem_u32(const void* p) {
    uint32_t a;
    asm("{ .reg .u64 t; cvta.to.shared.u64 t, %1; cvt.u32.u64 %0, t; }" : "=r"(a) : "l"(p));
    return a;
}
__device__ __forceinline__ void cp16(uint32_t dst, const void* src) {
    asm volatile("cp.async.ca.shared.global [%0], [%1], 16;" :: "r"(dst), "l"(src));
}

// ---------------- Kernel A: STFT (fp64-exact, f32-rounded) + top-32 --------
__global__ void k_stft(const float* __restrict__ x) {
    __shared__ float  s_s[SEQ];
    __shared__ float  win_s[NFFT];
    __shared__ double cosd[NFFT], sind[NFFT];
    __shared__ float  Sre[WN*FB], Sim[WN*FB], Sab[WN*FB];
    int blk = blockIdx.x;
    int b = blk >> 5, n = blk & 31;
    int tid = threadIdx.x;          // 128

    for (int t = tid; t < SEQ; t += 128) s_s[t] = x[(b*SEQ + t)*NFch + n];
    for (int t = tid; t < NFFT; t += 128) {
        float a = TWO_PI * (float)t / (float)NFFT;
        win_s[t] = 0.5f - 0.5f * (float)cos((double)a);
        double ad = TWO_PI_D * (double)t / 64.0;
        cosd[t] = cos(ad); sind[t] = sin(ad);
    }
    __syncthreads();

    for (int task = tid; task < WN*FB; task += 128) {
        int w = task / FB, f = task % FB;
        double re = 0.0, im = 0.0;
        for (int k = 0; k < NFFT; k++) {
            float v = s_s[reflect_t(w*HOPL + k)] * win_s[k];
            int a = (f*k) & 63;
            re = fma((double)v,  cosd[a], re);
            im = fma((double)v, -sind[a], im);
        }
        float rf = (float)re, imf = (float)im;
        Sre[task] = rf; Sim[task] = imf;
        Sab[task] = (float)sqrt((double)rf*rf + (double)imf*imf);
    }
    __syncthreads();

    if (tid < WN) {
        int w = tid;
        float mag[FB]; bool used[FB];
        for (int f = 0; f < FB; f++) { mag[f] = Sab[w*FB+f]; used[f] = false; }
        int base = (blk*WN + w) * TOPM;
        for (int m = 0; m < TOPM; m++) {
            int best = 0; float bv = -1.f;
            for (int f = 0; f < FB; f++)
                if (!used[f] && mag[f] > bv) { bv = mag[f]; best = f; }
            used[best] = true;
            g_fidx[base+m] = best;
            g_c[base+m] = make_float2(Sre[w*FB+best], Sim[w*FB+best]);
        }
    }
}

// ---------------- Kernel B: v[k][w][f] = sum_e emb[e]*Wk[w,e,f] ------------
__global__ void k_vred(const float* __restrict__ emb,
                       const float* __restrict__ Wr,  const float* __restrict__ Wi,
                       const float* __restrict__ Wrl, const float* __restrict__ Wil,
                       const float* __restrict__ Wrr, const float* __restrict__ Wir) {
    int k = blockIdx.x / WN, w = blockIdx.x % WN;
    const float* Wm = (k==0)?Wr:(k==1)?Wi:(k==2)?Wrl:(k==3)?Wil:(k==4)?Wrr:Wir;
    int f = threadIdx.x;
    const float* base = Wm + (size_t)w*ECH*ECH + f;
    float acc = 0.f;
    #pragma unroll 4
    for (int e = 0; e < ECH; e++) acc = fmaf(emb[e], base[(size_t)e*ECH], acc);
    g_v[(k*WN + w)*ECH + f] = acc;
}

// ---------------- Kernel C: fused Y + scatter + irfft + OLA + bias ---------
#define SMEM_MAIN 94976
__global__ void k_main(const float* __restrict__ x, const float* __restrict__ emb,
                       const float* __restrict__ br, const float* __restrict__ bi) {
    extern __shared__ char smraw[];
    float2* tab     = (float2*)(smraw);
    float*  full_re = (float*) (smraw + 16896);
    float*  full_im = (float*) (smraw + 33792);
    float*  ring    = (float*) (smraw + 50688);
    float2* cc      = (float2*)(smraw + 83456);
    float*  vs      = (float*) (smraw + 87808);
    float*  win_s   = (float*) (smraw + 91904);
    float*  ienv    = (float*) (smraw + 92160);
    float*  emb_s   = (float*) (smraw + 92288);
    int*    fidx_s  = (int*)   (smraw + 92800);

    int tid = threadIdx.x;          // 256
    int blk = blockIdx.x;
    int b = blk >> 5, n = blk & 31;

    for (int i = tid; i < FB*NFFT; i += 256) {
        int f = i >> 6, t = i & 63;
        double ad = TWO_PI_D * (double)((f*t) & 63) / 64.0;
        tab[i] = make_float2((float)cos(ad), (float)sin(ad));
    }
    for (int i = tid; i < NFFT; i += 256) {
        float a = TWO_PI * (float)i / (float)NFFT;
        win_s[i] = 0.5f - 0.5f * (float)cos((double)a);
    }
    for (int i = tid; i < HOPL; i += 256) {
        float a = TWO_PI * (float)i / (float)NFFT;
        float c = (float)cos((double)a);
        float w0 = 0.5f - 0.5f*c, w1 = 0.5f + 0.5f*c;
        ienv[i] = 1.0f / (w0*w0 + w1*w1);
    }
    for (int i = tid; i < ECH; i += 256) emb_s[i] = emb[i];
    for (int i = tid; i < WN*TOPM; i += 256) {
        cc[i]     = g_c[blk*WN*TOPM + i];
        fidx_s[i] = g_fidx[blk*WN*TOPM + i];
    }
    __syncthreads();

    int e0 = (tid & 31) << 2;
    int t0 = (tid >> 5) << 3;

    for (int w = 0; w < WN; w++) {
        for (int i = tid; i < 6*ECH; i += 256) {
            int k = i >> 7, e = i & 127;
            vs[i] = g_v[(k*WN + w)*ECH + e];
        }
        for (int i = tid; i < ECH; i += 256) {
            vs[6*ECH + i] = br[w*ECH + i];
            vs[7*ECH + i] = bi[w*ECH + i];
        }
        for (int i = tid; i < ECH*FB; i += 256) { full_re[i] = 0.f; full_im[i] = 0.f; }
        __syncthreads();

        for (int i = tid; i < ECH*TOPM; i += 256) {
            int m = i >> 7, e = i & 127;
            float2 c0 = cc[w*TOPM + m];
            float2 cl = (w > 0)    ? cc[(w-1)*TOPM + m] : make_float2(0.f,0.f);
            float2 cr = (w < WN-1) ? cc[(w+1)*TOPM + m] : make_float2(0.f,0.f);
            float vr  = vs[e],        vi  = vs[ECH+e];
            float vrl = vs[2*ECH+e],  vil = vs[3*ECH+e];
            float vrr = vs[4*ECH+e],  vir = vs[5*ECH+e];
            float ore = c0.x*vr - c0.y*vi + cl.x*vrl - cl.y*vil + cr.x*vrr - cr.y*vir + vs[6*ECH+e];
            float oim = c0.y*vr + c0.x*vi + cl.y*vrl + cl.x*vil + cr.y*vrr + cr.x*vir + vs[7*ECH+e];
            float yre = fmaxf(fmaxf(ore, 0.f) - LAMB, 0.f);
            float yim = fmaxf(fmaxf(oim, 0.f) - LAMB, 0.f);
            int f = fidx_s[w*TOPM + m];
            if (f == 0 || f == FB-1) {
                full_re[f*ECH + e] = yre * 0.015625f;
                full_im[f*ECH + e] = 0.f;
            } else {
                full_re[f*ECH + e] = yre * 0.03125f;
                full_im[f*ECH + e] = yim * 0.03125f;
            }
        }
        __syncthreads();

        float acc[4][8];
        #pragma unroll
        for (int jj = 0; jj < 4; jj++)
            #pragma unroll
            for (int kk = 0; kk < 8; kk++) acc[jj][kk] = 0.f;

        for (int f = 0; f < FB; f++) {
            float4 yr = *(const float4*)&full_re[f*ECH + e0];
            float4 yi = *(const float4*)&full_im[f*ECH + e0];
            float yra[4] = {yr.x, yr.y, yr.z, yr.w};
            float yia[4] = {yi.x, yi.y, yi.z, yi.w};
            #pragma unroll
            for (int kk = 0; kk < 8; kk++) {
                float2 ct = tab[f*NFFT + t0 + kk];
                #pragma unroll
                for (int jj = 0; jj < 4; jj++)
                    acc[jj][kk] = fmaf(yra[jj], ct.x, fmaf(-yia[jj], ct.y, acc[jj][kk]));
            }
        }

        #pragma unroll
        for (int kk = 0; kk < 8; kk++) {
            int t = t0 + kk;
            int slot = (w*HOPL + t) & 63;
            float wm = win_s[t];
            float4* rp = (float4*)&ring[slot*ECH + e0];
            float4 v;
            v.x = acc[0][kk]*wm; v.y = acc[1][kk]*wm;
            v.z = acc[2][kk]*wm; v.w = acc[3][kk]*wm;
            if (t < HOPL && w > 0) {
                float4 o = *rp;
                v.x += o.x; v.y += o.y; v.z += o.z; v.w += o.w;
            }
            *rp = v;
        }
        __syncthreads();

        if (w > 0) {
            for (int i = tid; i < HOPL*ECH; i += 256) {
                int r = i >> 7, e = i & 127;
                int t_out = (w-1)*HOPL + r;
                int slot = (w*HOPL + r) & 63;
                float val = ring[slot*ECH + e] * ienv[r]
                          + x[(b*SEQ + t_out)*NFch + n] * emb_s[e];
                g_xo[(size_t)blk*KTOT + t_out*ECH + e] = val;
            }
        }
        __syncthreads();
    }
}

// ---------------- Kernel D: FC1 split-K, 3xTF32 tensor-core GEMM -----------
// Raw fp32 smem tiles (halved smem + crossbar), cp.async double-buffer,
// hi/lo tf32 split at fragment load, 2 CTAs/SM.
#define SA 36
#define SB 136
#define STAGE_A (128*SA)            // floats
#define STAGE_B (BK*SB)
#define STAGE_F (STAGE_A + STAGE_B) // 8960 floats = 35840 B
#define SMEM_FC1 (2*STAGE_F*4)      // 71680 B
__global__ __launch_bounds__(256, 2) void k_fc1(const float* __restrict__ w1) {
    extern __shared__ float sm[];

    int m0 = blockIdx.x * 128, n0 = blockIdx.y * 128;
    int kbase = blockIdx.z * KCHUNK;
    int tid = threadIdx.x, lane = tid & 31, wid = tid >> 5;
    int wm = wid >> 1, wn = wid & 1;          // warp tile: 32(M) x 64(N)
    int ra = lane >> 2, ca = lane & 3;

    float acc[2][8][4];
    #pragma unroll
    for (int i = 0; i < 2; i++)
        #pragma unroll
        for (int j = 0; j < 8; j++)
            #pragma unroll
            for (int q = 0; q < 4; q++) acc[i][j][q] = 0.f;

    // per-thread cp.async coordinates (4 A-chunks + 4 B-chunks of 16B)
    int am[4], ak[4], bk[4], bn[4];
    #pragma unroll
    for (int i = 0; i < 4; i++) {
        int c = tid + i*256;
        am[i] = c >> 3;  ak[i] = (c & 7) * 4;
        bk[i] = c >> 5;  bn[i] = (c & 31) * 4;
    }

    uint32_t smA[2], smB[2];
    smA[0] = smem_u32(sm);
    smB[0] = smA[0] + STAGE_A*4;
    smA[1] = smA[0] + STAGE_F*4;
    smB[1] = smB[0] + STAGE_F*4;

    // prologue: stage 0
    {
        int kc = kbase;
        #pragma unroll
        for (int i = 0; i < 4; i++) {
            cp16(smA[0] + (am[i]*SA + ak[i])*4, &g_xo[(size_t)(m0+am[i])*KTOT + kc + ak[i]]);
            cp16(smB[0] + (bk[i]*SB + bn[i])*4, &w1[(size_t)(kc+bk[i])*HID + n0 + bn[i]]);
        }
        asm volatile("cp.async.commit_group;");
    }

    for (int it = 0; it < NSTAGE; it++) {
        if (it + 1 < NSTAGE) {
            int buf = (it+1) & 1;
            int kc = kbase + (it+1)*BK;
            #pragma unroll
            for (int i = 0; i < 4; i++) {
                cp16(smA[buf] + (am[i]*SA + ak[i])*4, &g_xo[(size_t)(m0+am[i])*KTOT + kc + ak[i]]);
                cp16(smB[buf] + (bk[i]*SB + bn[i])*4, &w1[(size_t)(kc+bk[i])*HID + n0 + bn[i]]);
            }
            asm volatile("cp.async.commit_group;");
            asm volatile("cp.async.wait_group 1;");
        } else {
            asm volatile("cp.async.wait_group 0;");
        }
        __syncthreads();

        const float* As = sm + (it & 1) * STAGE_F;
        const float* Bs = As + STAGE_A;

        #pragma unroll
        for (int ks = 0; ks < BK/8; ks++) {
            int k0 = ks*8 + ca;
            uint32_t ah[2][4], al[2][4];
            #pragma unroll
            for (int i = 0; i < 2; i++) {
                int mb = wm*32 + i*16;
                float v0 = As[(mb+ra  )*SA + k0  ];
                float v1 = As[(mb+ra+8)*SA + k0  ];
                float v2 = As[(mb+ra  )*SA + k0+4];
                float v3 = As[(mb+ra+8)*SA + k0+4];
                ah[i][0] = f2tf32u(v0); al[i][0] = f2tf32u(v0 - __uint_as_float(ah[i][0]));
                ah[i][1] = f2tf32u(v1); al[i][1] = f2tf32u(v1 - __uint_as_float(ah[i][1]));
                ah[i][2] = f2tf32u(v2); al[i][2] = f2tf32u(v2 - __uint_as_float(ah[i][2]));
                ah[i][3] = f2tf32u(v3); al[i][3] = f2tf32u(v3 - __uint_as_float(ah[i][3]));
            }
            #pragma unroll
            for (int j = 0; j < 8; j++) {
                int nb = wn*64 + j*8 + ra;
                float w0 = Bs[(k0  )*SB + nb];
                float w1v = Bs[(k0+4)*SB + nb];
                uint32_t bh[2], bl[2];
                bh[0] = f2tf32u(w0);  bl[0] = f2tf32u(w0  - __uint_as_float(bh[0]));
                bh[1] = f2tf32u(w1v); bl[1] = f2tf32u(w1v - __uint_as_float(bh[1]));
                #pragma unroll
                for (int i = 0; i < 2; i++) {
                    mma_tf32(acc[i][j], al[i], bh);   // small terms first
                    mma_tf32(acc[i][j], ah[i], bl);
                    mma_tf32(acc[i][j], ah[i], bh);
                }
            }
        }
        __syncthreads();
    }

    // epilogue: write split-K partials (deterministic reduction in k_hred)
    size_t base = (size_t)blockIdx.z * (ROWS*HID);
    #pragma unroll
    for (int i = 0; i < 2; i++) {
        #pragma unroll
        for (int j = 0; j < 8; j++) {
            int row = m0 + wm*32 + i*16 + ra;
            int col = n0 + wn*64 + j*8 + ca*2;
            *(float2*)&g_Hpart[base + (size_t)row*HID + col]     = make_float2(acc[i][j][0], acc[i][j][1]);
            *(float2*)&g_Hpart[base + (size_t)(row+8)*HID + col] = make_float2(acc[i][j][2], acc[i][j][3]);
        }
    }
}

__global__ void k_hred() {
    int i = blockIdx.x * 256 + threadIdx.x;
    if (i >= ROWS*HID) return;
    float s = 0.f;
    #pragma unroll
    for (int z = 0; z < KSPLIT; z++) s += g_Hpart[(size_t)z*(ROWS*HID) + i];
    g_H[i] = s;
}

// ---------------- Kernel E: leaky_relu + FC2 + output transpose ------------
__global__ void k_fc2(const float* __restrict__ b1, const float* __restrict__ w2,
                      const float* __restrict__ b2, float* __restrict__ out) {
    __shared__ float hrow[HID];
    int row = blockIdx.x;
    int tid = threadIdx.x;          // 96
    for (int i = tid; i < HID; i += PRED) {
        float v = g_H[row*HID + i] + b1[i];
        hrow[i] = v > 0.f ? v : 0.01f * v;
    }
    __syncthreads();
    int b = row >> 5, n = row & 31;
    float acc = b2[tid];
    #pragma unroll 4
    for (int h = 0; h < HID; h++) acc = fmaf(hrow[h], w2[h*PRED + tid], acc);
    out[(b*PRED + tid)*NFch + n] = acc;
}

// ---------------------------------------------------------------------------
extern "C" void kernel_launch(void* const* d_in, const int* in_sizes, int n_in,
                              void* d_out, int out_size) {
    const float* x   = (const float*)d_in[0];
    const float* emb = (const float*)d_in[1];
    const float* br  = (const float*)d_in[8];
    const float* bi  = (const float*)d_in[9];
    const float* w1  = (const float*)d_in[10];
    const float* b1  = (const float*)d_in[11];
    const float* w2  = (const float*)d_in[12];
    const float* b2  = (const float*)d_in[13];
    float* out = (float*)d_out;

    cudaFuncSetAttribute(k_main, cudaFuncAttributeMaxDynamicSharedMemorySize, SMEM_MAIN);
    cudaFuncSetAttribute(k_fc1,  cudaFuncAttributeMaxDynamicSharedMemorySize, SMEM_FC1);

    k_stft<<<ROWS, 128>>>(x);
    k_vred<<<6*WN, 128>>>(emb, (const float*)d_in[2], (const float*)d_in[3],
                          (const float*)d_in[4], (const float*)d_in[5],
                          (const float*)d_in[6], (const float*)d_in[7]);
    k_main<<<ROWS, 256, SMEM_MAIN>>>(x, emb, br, bi);
    k_fc1<<<dim3(4, 4, KSPLIT), 256, SMEM_FC1>>>(w1);
    k_hred<<<(ROWS*HID + 255)/256, 256>>>();
    k_fc2<<<ROWS, PRED>>>(b1, w2, b2, out);
}

// round 7
// speedup vs baseline: 2.8002x; 1.3894x over previous
#include <cuda_runtime.h>
#include <math.h>
#include <stdint.h>

#define BQ    16
#define SEQ   512
#define NFch  32
#define ECH   128
#define HID   512
#define PRED  96
#define NFFT  64
#define HOPL  32
#define TOPM  32
#define WN    17
#define FB    33
#define LAMB  0.01f

#define ROWS  (BQ*NFch)      // 512  (b*32+n)
#define KTOT  (SEQ*ECH)      // 65536
#define KSPLIT 32
#define KCHUNK (KTOT/KSPLIT) // 2048
#define BK    32
#define NSTAGE (KCHUNK/BK)   // 64

// ---------------- scratch (static device globals; no runtime alloc) --------
__device__ float2 g_c[ROWS*WN*TOPM];
__device__ int    g_fidx[ROWS*WN*TOPM];
__device__ float  g_v[6*WN*ECH];
__device__ float  g_xo[(size_t)ROWS*KTOT];          // tf32-rounded, ~134MB
__device__ float  g_Hpart[(size_t)KSPLIT*ROWS*HID];
__device__ float  g_H[ROWS*HID];

#define TWO_PI 6.28318530717958647692f
#define TWO_PI_D 6.28318530717958647692528676655900577

__device__ __forceinline__ int reflect_t(int j) {
    int t = j - 32;
    if (t < 0) t = -t;
    else if (t > SEQ-1) t = 2*(SEQ-1) - t;
    return t;
}

__device__ __forceinline__ uint32_t f2tf32u(float f) {
    uint32_t r; asm("cvt.rna.tf32.f32 %0, %1;" : "=r"(r) : "f"(f)); return r;
}

__device__ __forceinline__ void mma_tf32(float* c, const uint32_t* a, const uint32_t* b) {
    asm volatile("mma.sync.aligned.m16n8k8.row.col.f32.tf32.tf32.f32 "
        "{%0,%1,%2,%3}, {%4,%5,%6,%7}, {%8,%9}, {%0,%1,%2,%3};"
        : "+f"(c[0]), "+f"(c[1]), "+f"(c[2]), "+f"(c[3])
        : "r"(a[0]), "r"(a[1]), "r"(a[2]), "r"(a[3]), "r"(b[0]), "r"(b[1]));
}

__device__ __forceinline__ uint32_t smem_u32(const void* p) {
    uint32_t a;
    asm("{ .reg .u64 t; cvta.to.shared.u64 t, %1; cvt.u32.u64 %0, t; }" : "=r"(a) : "l"(p));
    return a;
}
__device__ __forceinline__ void cp16(uint32_t dst, const void* src) {
    asm volatile("cp.async.ca.shared.global [%0], [%1], 16;" :: "r"(dst), "l"(src));
}

// ---------------- Kernel A: STFT (fp64-exact, f32-rounded) + top-32 --------
__global__ void k_stft(const float* __restrict__ x) {
    __shared__ float  s_s[SEQ];
    __shared__ float  win_s[NFFT];
    __shared__ double cosd[NFFT], sind[NFFT];
    __shared__ float  Sre[WN*FB], Sim[WN*FB], Sab[WN*FB];
    int blk = blockIdx.x;
    int b = blk >> 5, n = blk & 31;
    int tid = threadIdx.x;          // 128

    for (int t = tid; t < SEQ; t += 128) s_s[t] = x[(b*SEQ + t)*NFch + n];
    for (int t = tid; t < NFFT; t += 128) {
        float a = TWO_PI * (float)t / (float)NFFT;
        win_s[t] = 0.5f - 0.5f * (float)cos((double)a);
        double ad = TWO_PI_D * (double)t / 64.0;
        cosd[t] = cos(ad); sind[t] = sin(ad);
    }
    __syncthreads();

    for (int task = tid; task < WN*FB; task += 128) {
        int w = task / FB, f = task % FB;
        double re = 0.0, im = 0.0;
        for (int k = 0; k < NFFT; k++) {
            float v = s_s[reflect_t(w*HOPL + k)] * win_s[k];
            int a = (f*k) & 63;
            re = fma((double)v,  cosd[a], re);
            im = fma((double)v, -sind[a], im);
        }
        float rf = (float)re, imf = (float)im;
        Sre[task] = rf; Sim[task] = imf;
        Sab[task] = (float)sqrt((double)rf*rf + (double)imf*imf);
    }
    __syncthreads();

    if (tid < WN) {
        int w = tid;
        float mag[FB]; bool used[FB];
        for (int f = 0; f < FB; f++) { mag[f] = Sab[w*FB+f]; used[f] = false; }
        int base = (blk*WN + w) * TOPM;
        for (int m = 0; m < TOPM; m++) {
            int best = 0; float bv = -1.f;
            for (int f = 0; f < FB; f++)
                if (!used[f] && mag[f] > bv) { bv = mag[f]; best = f; }
            used[best] = true;
            g_fidx[base+m] = best;
            g_c[base+m] = make_float2(Sre[w*FB+best], Sim[w*FB+best]);
        }
    }
}

// ---------------- Kernel B: v[k][w][f] = sum_e emb[e]*Wk[w,e,f] ------------
__global__ void k_vred(const float* __restrict__ emb,
                       const float* __restrict__ Wr,  const float* __restrict__ Wi,
                       const float* __restrict__ Wrl, const float* __restrict__ Wil,
                       const float* __restrict__ Wrr, const float* __restrict__ Wir) {
    int k = blockIdx.x / WN, w = blockIdx.x % WN;
    const float* Wm = (k==0)?Wr:(k==1)?Wi:(k==2)?Wrl:(k==3)?Wil:(k==4)?Wrr:Wir;
    int f = threadIdx.x;
    const float* base = Wm + (size_t)w*ECH*ECH + f;
    float acc = 0.f;
    #pragma unroll 4
    for (int e = 0; e < ECH; e++) acc = fmaf(emb[e], base[(size_t)e*ECH], acc);
    g_v[(k*WN + w)*ECH + f] = acc;
}

// ---------------- Kernel C: fused Y + scatter + irfft + OLA + bias ---------
#define SMEM_MAIN 94976
__global__ void k_main(const float* __restrict__ x, const float* __restrict__ emb,
                       const float* __restrict__ br, const float* __restrict__ bi) {
    extern __shared__ char smraw[];
    float2* tab     = (float2*)(smraw);
    float*  full_re = (float*) (smraw + 16896);
    float*  full_im = (float*) (smraw + 33792);
    float*  ring    = (float*) (smraw + 50688);
    float2* cc      = (float2*)(smraw + 83456);
    float*  vs      = (float*) (smraw + 87808);
    float*  win_s   = (float*) (smraw + 91904);
    float*  ienv    = (float*) (smraw + 92160);
    float*  emb_s   = (float*) (smraw + 92288);
    int*    fidx_s  = (int*)   (smraw + 92800);

    int tid = threadIdx.x;          // 256
    int blk = blockIdx.x;
    int b = blk >> 5, n = blk & 31;

    for (int i = tid; i < FB*NFFT; i += 256) {
        int f = i >> 6, t = i & 63;
        double ad = TWO_PI_D * (double)((f*t) & 63) / 64.0;
        tab[i] = make_float2((float)cos(ad), (float)sin(ad));
    }
    for (int i = tid; i < NFFT; i += 256) {
        float a = TWO_PI * (float)i / (float)NFFT;
        win_s[i] = 0.5f - 0.5f * (float)cos((double)a);
    }
    for (int i = tid; i < HOPL; i += 256) {
        float a = TWO_PI * (float)i / (float)NFFT;
        float c = (float)cos((double)a);
        float w0 = 0.5f - 0.5f*c, w1 = 0.5f + 0.5f*c;
        ienv[i] = 1.0f / (w0*w0 + w1*w1);
    }
    for (int i = tid; i < ECH; i += 256) emb_s[i] = emb[i];
    for (int i = tid; i < WN*TOPM; i += 256) {
        cc[i]     = g_c[blk*WN*TOPM + i];
        fidx_s[i] = g_fidx[blk*WN*TOPM + i];
    }
    __syncthreads();

    int e0 = (tid & 31) << 2;
    int t0 = (tid >> 5) << 3;

    for (int w = 0; w < WN; w++) {
        for (int i = tid; i < 6*ECH; i += 256) {
            int k = i >> 7, e = i & 127;
            vs[i] = g_v[(k*WN + w)*ECH + e];
        }
        for (int i = tid; i < ECH; i += 256) {
            vs[6*ECH + i] = br[w*ECH + i];
            vs[7*ECH + i] = bi[w*ECH + i];
        }
        for (int i = tid; i < ECH*FB; i += 256) { full_re[i] = 0.f; full_im[i] = 0.f; }
        __syncthreads();

        for (int i = tid; i < ECH*TOPM; i += 256) {
            int m = i >> 7, e = i & 127;
            float2 c0 = cc[w*TOPM + m];
            float2 cl = (w > 0)    ? cc[(w-1)*TOPM + m] : make_float2(0.f,0.f);
            float2 cr = (w < WN-1) ? cc[(w+1)*TOPM + m] : make_float2(0.f,0.f);
            float vr  = vs[e],        vi  = vs[ECH+e];
            float vrl = vs[2*ECH+e],  vil = vs[3*ECH+e];
            float vrr = vs[4*ECH+e],  vir = vs[5*ECH+e];
            float ore = c0.x*vr - c0.y*vi + cl.x*vrl - cl.y*vil + cr.x*vrr - cr.y*vir + vs[6*ECH+e];
            float oim = c0.y*vr + c0.x*vi + cl.y*vrl + cl.x*vil + cr.y*vrr + cr.x*vir + vs[7*ECH+e];
            float yre = fmaxf(fmaxf(ore, 0.f) - LAMB, 0.f);
            float yim = fmaxf(fmaxf(oim, 0.f) - LAMB, 0.f);
            int f = fidx_s[w*TOPM + m];
            if (f == 0 || f == FB-1) {
                full_re[f*ECH + e] = yre * 0.015625f;
                full_im[f*ECH + e] = 0.f;
            } else {
                full_re[f*ECH + e] = yre * 0.03125f;
                full_im[f*ECH + e] = yim * 0.03125f;
            }
        }
        __syncthreads();

        float acc[4][8];
        #pragma unroll
        for (int jj = 0; jj < 4; jj++)
            #pragma unroll
            for (int kk = 0; kk < 8; kk++) acc[jj][kk] = 0.f;

        for (int f = 0; f < FB; f++) {
            float4 yr = *(const float4*)&full_re[f*ECH + e0];
            float4 yi = *(const float4*)&full_im[f*ECH + e0];
            float yra[4] = {yr.x, yr.y, yr.z, yr.w};
            float yia[4] = {yi.x, yi.y, yi.z, yi.w};
            #pragma unroll
            for (int kk = 0; kk < 8; kk++) {
                float2 ct = tab[f*NFFT + t0 + kk];
                #pragma unroll
                for (int jj = 0; jj < 4; jj++)
                    acc[jj][kk] = fmaf(yra[jj], ct.x, fmaf(-yia[jj], ct.y, acc[jj][kk]));
            }
        }

        #pragma unroll
        for (int kk = 0; kk < 8; kk++) {
            int t = t0 + kk;
            int slot = (w*HOPL + t) & 63;
            float wm = win_s[t];
            float4* rp = (float4*)&ring[slot*ECH + e0];
            float4 v;
            v.x = acc[0][kk]*wm; v.y = acc[1][kk]*wm;
            v.z = acc[2][kk]*wm; v.w = acc[3][kk]*wm;
            if (t < HOPL && w > 0) {
                float4 o = *rp;
                v.x += o.x; v.y += o.y; v.z += o.z; v.w += o.w;
            }
            *rp = v;
        }
        __syncthreads();

        if (w > 0) {
            for (int i = tid; i < HOPL*ECH; i += 256) {
                int r = i >> 7, e = i & 127;
                int t_out = (w-1)*HOPL + r;
                int slot = (w*HOPL + r) & 63;
                float val = ring[slot*ECH + e] * ienv[r]
                          + x[(b*SEQ + t_out)*NFch + n] * emb_s[e];
                // pre-round to tf32: g_xo feeds only the TF32 FC1 GEMM
                g_xo[(size_t)blk*KTOT + t_out*ECH + e] = __uint_as_float(f2tf32u(val));
            }
        }
        __syncthreads();
    }
}

// ---------------- Kernel D: FC1 split-K, 1xTF32 tensor-core GEMM -----------
// A (g_xo) is pre-rounded to tf32 by k_main; B cvt'd inline at fragment load.
#define SA 36
#define SB 136
#define STAGE_A (128*SA)            // floats
#define STAGE_B (BK*SB)
#define STAGE_F (STAGE_A + STAGE_B) // 8960 floats = 35840 B
#define SMEM_FC1 (2*STAGE_F*4)      // 71680 B
__global__ __launch_bounds__(256, 2) void k_fc1(const float* __restrict__ w1) {
    extern __shared__ float sm[];

    int m0 = blockIdx.x * 128, n0 = blockIdx.y * 128;
    int kbase = blockIdx.z * KCHUNK;
    int tid = threadIdx.x, lane = tid & 31, wid = tid >> 5;
    int wm = wid >> 1, wn = wid & 1;          // warp tile: 32(M) x 64(N)
    int ra = lane >> 2, ca = lane & 3;

    float acc[2][8][4];
    #pragma unroll
    for (int i = 0; i < 2; i++)
        #pragma unroll
        for (int j = 0; j < 8; j++)
            #pragma unroll
            for (int q = 0; q < 4; q++) acc[i][j][q] = 0.f;

    int am[4], ak[4], bk[4], bn[4];
    #pragma unroll
    for (int i = 0; i < 4; i++) {
        int c = tid + i*256;
        am[i] = c >> 3;  ak[i] = (c & 7) * 4;
        bk[i] = c >> 5;  bn[i] = (c & 31) * 4;
    }

    uint32_t smA[2], smB[2];
    smA[0] = smem_u32(sm);
    smB[0] = smA[0] + STAGE_A*4;
    smA[1] = smA[0] + STAGE_F*4;
    smB[1] = smB[0] + STAGE_F*4;

    {
        int kc = kbase;
        #pragma unroll
        for (int i = 0; i < 4; i++) {
            cp16(smA[0] + (am[i]*SA + ak[i])*4, &g_xo[(size_t)(m0+am[i])*KTOT + kc + ak[i]]);
            cp16(smB[0] + (bk[i]*SB + bn[i])*4, &w1[(size_t)(kc+bk[i])*HID + n0 + bn[i]]);
        }
        asm volatile("cp.async.commit_group;");
    }

    for (int it = 0; it < NSTAGE; it++) {
        if (it + 1 < NSTAGE) {
            int buf = (it+1) & 1;
            int kc = kbase + (it+1)*BK;
            #pragma unroll
            for (int i = 0; i < 4; i++) {
                cp16(smA[buf] + (am[i]*SA + ak[i])*4, &g_xo[(size_t)(m0+am[i])*KTOT + kc + ak[i]]);
                cp16(smB[buf] + (bk[i]*SB + bn[i])*4, &w1[(size_t)(kc+bk[i])*HID + n0 + bn[i]]);
            }
            asm volatile("cp.async.commit_group;");
            asm volatile("cp.async.wait_group 1;");
        } else {
            asm volatile("cp.async.wait_group 0;");
        }
        __syncthreads();

        const float* As = sm + (it & 1) * STAGE_F;
        const float* Bs = As + STAGE_A;

        #pragma unroll
        for (int ks = 0; ks < BK/8; ks++) {
            int k0 = ks*8 + ca;
            uint32_t ah[2][4];
            #pragma unroll
            for (int i = 0; i < 2; i++) {
                int mb = wm*32 + i*16;
                ah[i][0] = __float_as_uint(As[(mb+ra  )*SA + k0  ]);   // already tf32
                ah[i][1] = __float_as_uint(As[(mb+ra+8)*SA + k0  ]);
                ah[i][2] = __float_as_uint(As[(mb+ra  )*SA + k0+4]);
                ah[i][3] = __float_as_uint(As[(mb+ra+8)*SA + k0+4]);
            }
            #pragma unroll
            for (int j = 0; j < 8; j++) {
                int nb = wn*64 + j*8 + ra;
                uint32_t bh[2];
                bh[0] = f2tf32u(Bs[(k0  )*SB + nb]);
                bh[1] = f2tf32u(Bs[(k0+4)*SB + nb]);
                #pragma unroll
                for (int i = 0; i < 2; i++)
                    mma_tf32(acc[i][j], ah[i], bh);
            }
        }
        __syncthreads();
    }

    size_t base = (size_t)blockIdx.z * (ROWS*HID);
    #pragma unroll
    for (int i = 0; i < 2; i++) {
        #pragma unroll
        for (int j = 0; j < 8; j++) {
            int row = m0 + wm*32 + i*16 + ra;
            int col = n0 + wn*64 + j*8 + ca*2;
            *(float2*)&g_Hpart[base + (size_t)row*HID + col]     = make_float2(acc[i][j][0], acc[i][j][1]);
            *(float2*)&g_Hpart[base + (size_t)(row+8)*HID + col] = make_float2(acc[i][j][2], acc[i][j][3]);
        }
    }
}

__global__ void k_hred() {
    int i = blockIdx.x * 256 + threadIdx.x;
    if (i >= ROWS*HID) return;
    float s = 0.f;
    #pragma unroll
    for (int z = 0; z < KSPLIT; z++) s += g_Hpart[(size_t)z*(ROWS*HID) + i];
    g_H[i] = s;
}

// ---------------- Kernel E: leaky_relu + FC2 (exact fp32) + transpose ------
__global__ void k_fc2(const float* __restrict__ b1, const float* __restrict__ w2,
                      const float* __restrict__ b2, float* __restrict__ out) {
    __shared__ float hrow[HID];
    int row = blockIdx.x;
    int tid = threadIdx.x;          // 96
    for (int i = tid; i < HID; i += PRED) {
        float v = g_H[row*HID + i] + b1[i];
        hrow[i] = v > 0.f ? v : 0.01f * v;
    }
    __syncthreads();
    int b = row >> 5, n = row & 31;
    float acc = b2[tid];
    #pragma unroll 4
    for (int h = 0; h < HID; h++) acc = fmaf(hrow[h], w2[h*PRED + tid], acc);
    out[(b*PRED + tid)*NFch + n] = acc;
}

// ---------------------------------------------------------------------------
extern "C" void kernel_launch(void* const* d_in, const int* in_sizes, int n_in,
                              void* d_out, int out_size) {
    const float* x   = (const float*)d_in[0];
    const float* emb = (const float*)d_in[1];
    const float* br  = (const float*)d_in[8];
    const float* bi  = (const float*)d_in[9];
    const float* w1  = (const float*)d_in[10];
    const float* b1  = (const float*)d_in[11];
    const float* w2  = (const float*)d_in[12];
    const float* b2  = (const float*)d_in[13];
    float* out = (float*)d_out;

    cudaFuncSetAttribute(k_main, cudaFuncAttributeMaxDynamicSharedMemorySize, SMEM_MAIN);
    cudaFuncSetAttribute(k_fc1,  cudaFuncAttributeMaxDynamicSharedMemorySize, SMEM_FC1);

    k_stft<<<ROWS, 128>>>(x);
    k_vred<<<6*WN, 128>>>(emb, (const float*)d_in[2], (const float*)d_in[3],
                          (const float*)d_in[4], (const float*)d_in[5],
                          (const float*)d_in[6], (const float*)d_in[7]);
    k_main<<<ROWS, 256, SMEM_MAIN>>>(x, emb, br, bi);
    k_fc1<<<dim3(4, 4, KSPLIT), 256, SMEM_FC1>>>(w1);
    k_hred<<<(ROWS*HID + 255)/256, 256>>>();
    k_fc2<<<ROWS, PRED>>>(b1, w2, b2, out);
}

// round 8
// speedup vs baseline: 3.0052x; 1.0732x over previous
#include <cuda_runtime.h>
#include <math.h>
#include <stdint.h>

#define BQ    16
#define SEQ   512
#define NFch  32
#define ECH   128
#define HID   512
#define PRED  96
#define NFFT  64
#define HOPL  32
#define TOPM  32
#define WN    17
#define FB    33
#define LAMB  0.01f

#define ROWS  (BQ*NFch)      // 512  (b*32+n)
#define KTOT  (SEQ*ECH)      // 65536
#define KSPLIT 32
#define KCHUNK (KTOT/KSPLIT) // 2048
#define BK    32
#define NSTAGE (KCHUNK/BK)   // 64

// ---------------- scratch (static device globals; no runtime alloc) --------
__device__ float2 g_c[ROWS*WN*TOPM];
__device__ int    g_fidx[ROWS*WN*TOPM];
__device__ float  g_v[6*WN*ECH];
__device__ float  g_xo[(size_t)ROWS*KTOT];          // tf32-rounded, ~134MB
__device__ float  g_Hpart[(size_t)KSPLIT*ROWS*HID];
__device__ float  g_H[ROWS*HID];

#define TWO_PI 6.28318530717958647692f
#define TWO_PI_D 6.28318530717958647692528676655900577

__device__ __forceinline__ int reflect_t(int j) {
    int t = j - 32;
    if (t < 0) t = -t;
    else if (t > SEQ-1) t = 2*(SEQ-1) - t;
    return t;
}

__device__ __forceinline__ uint32_t f2tf32u(float f) {
    uint32_t r; asm("cvt.rna.tf32.f32 %0, %1;" : "=r"(r) : "f"(f)); return r;
}

__device__ __forceinline__ void mma_tf32(float* c, const uint32_t* a, const uint32_t* b) {
    asm volatile("mma.sync.aligned.m16n8k8.row.col.f32.tf32.tf32.f32 "
        "{%0,%1,%2,%3}, {%4,%5,%6,%7}, {%8,%9}, {%0,%1,%2,%3};"
        : "+f"(c[0]), "+f"(c[1]), "+f"(c[2]), "+f"(c[3])
        : "r"(a[0]), "r"(a[1]), "r"(a[2]), "r"(a[3]), "r"(b[0]), "r"(b[1]));
}

__device__ __forceinline__ uint32_t smem_u32(const void* p) {
    uint32_t a;
    asm("{ .reg .u64 t; cvta.to.shared.u64 t, %1; cvt.u32.u64 %0, t; }" : "=r"(a) : "l"(p));
    return a;
}
__device__ __forceinline__ void cp16(uint32_t dst, const void* src) {
    asm volatile("cp.async.ca.shared.global [%0], [%1], 16;" :: "r"(dst), "l"(src));
}

// packed f32x2 helpers (Blackwell FFMA2; IEEE fp32 per lane)
__device__ __forceinline__ void fma2(unsigned long long& acc, unsigned long long a, unsigned long long b) {
    asm("fma.rn.f32x2 %0, %1, %2, %0;" : "+l"(acc) : "l"(a), "l"(b));
}
__device__ __forceinline__ unsigned long long pack2(float lo, float hi) {
    unsigned long long r; asm("mov.b64 %0, {%1, %2};" : "=l"(r) : "f"(lo), "f"(hi)); return r;
}

// ---------------- Kernel A: STFT (df64 fp32, exact twiddles) + top-32 ------
// Rank ORDER matters downstream; df64 accumulation (~1e-13 rel) keeps the
// spectrum within the cuFFT-deviation floor, at ~10x the fp64 pipe rate.
__global__ void k_stft(const float* __restrict__ x) {
    __shared__ float s_s[SEQ];
    __shared__ float win_s[NFFT];
    __shared__ float chi_s[NFFT], clo_s[NFFT];   // cos hi/lo
    __shared__ float mhi_s[NFFT], mlo_s[NFFT];   // (-sin) hi/lo
    __shared__ float Sre[WN*FB], Sim[WN*FB], Sab[WN*FB];
    int blk = blockIdx.x;
    int b = blk >> 5, n = blk & 31;
    int tid = threadIdx.x;          // 128

    for (int t = tid; t < SEQ; t += 128) s_s[t] = x[(b*SEQ + t)*NFch + n];
    for (int t = tid; t < NFFT; t += 128) {
        float a = TWO_PI * (float)t / (float)NFFT;
        win_s[t] = 0.5f - 0.5f * (float)cos((double)a);
        double ad = TWO_PI_D * (double)t / 64.0;
        double cd = cos(ad), msd = -sin(ad);
        float ch = (float)cd;  chi_s[t] = ch; clo_s[t] = (float)(cd - (double)ch);
        float mh = (float)msd; mhi_s[t] = mh; mlo_s[t] = (float)(msd - (double)mh);
    }
    __syncthreads();

    for (int task = tid; task < WN*FB; task += 128) {
        int w = task / FB, f = task % FB;
        float rh = 0.f, rl = 0.f, ih = 0.f, il = 0.f;
        for (int k = 0; k < NFFT; k++) {
            float v = s_s[reflect_t(w*HOPL + k)] * win_s[k];
            int a = (f*k) & 63;
            // real: v * cos
            float ch = chi_s[a];
            float ph = v * ch;
            float pe = fmaf(v, ch, -ph);
            pe = fmaf(v, clo_s[a], pe);
            float s  = rh + ph;
            float bb = s - rh;
            float er = (rh - (s - bb)) + (ph - bb);
            rh = s; rl += er + pe;
            // imag: v * (-sin)
            float mh = mhi_s[a];
            float qh = v * mh;
            float qe = fmaf(v, mh, -qh);
            qe = fmaf(v, mlo_s[a], qe);
            float s2  = ih + qh;
            float b2  = s2 - ih;
            float e2  = (ih - (s2 - b2)) + (qh - b2);
            ih = s2; il += e2 + qe;
        }
        float rf = rh + rl, imf = ih + il;
        Sre[task] = rf; Sim[task] = imf;
        Sab[task] = (float)sqrt((double)rf*rf + (double)imf*imf);
    }
    __syncthreads();

    if (tid < WN) {
        int w = tid;
        float mag[FB]; bool used[FB];
        for (int f = 0; f < FB; f++) { mag[f] = Sab[w*FB+f]; used[f] = false; }
        int base = (blk*WN + w) * TOPM;
        for (int m = 0; m < TOPM; m++) {
            int best = 0; float bv = -1.f;
            for (int f = 0; f < FB; f++)
                if (!used[f] && mag[f] > bv) { bv = mag[f]; best = f; }
            used[best] = true;
            g_fidx[base+m] = best;
            g_c[base+m] = make_float2(Sre[w*FB+best], Sim[w*FB+best]);
        }
    }
}

// ---------------- Kernel B: v[k][w][f] = sum_e emb[e]*Wk[w,e,f] ------------
__global__ void k_vred(const float* __restrict__ emb,
                       const float* __restrict__ Wr,  const float* __restrict__ Wi,
                       const float* __restrict__ Wrl, const float* __restrict__ Wil,
                       const float* __restrict__ Wrr, const float* __restrict__ Wir) {
    int k = blockIdx.x / WN, w = blockIdx.x % WN;
    const float* Wm = (k==0)?Wr:(k==1)?Wi:(k==2)?Wrl:(k==3)?Wil:(k==4)?Wrr:Wir;
    int f = threadIdx.x;
    const float* base = Wm + (size_t)w*ECH*ECH + f;
    float acc = 0.f;
    #pragma unroll 4
    for (int e = 0; e < ECH; e++) acc = fmaf(emb[e], base[(size_t)e*ECH], acc);
    g_v[(k*WN + w)*ECH + f] = acc;
}

// ---------------- Kernel C: fused Y + direct-topk irfft + OLA + bias -------
// smem layout (bytes):
//  tabc ull[2112]  @0       .. 16896   packed (c,c)
//  tabs ull[2112]  @16896   .. 33792   packed (-s,-s)
//  y_re float[4096]@33792   .. 50176
//  y_im float[4096]@50176   .. 66560
//  ring float[8192]@66560   .. 99328
//  cc   float2[544]@99328   .. 103680
//  vs   float[1024]@103680  .. 107776
//  win  float[64]  @107776
//  ienv float[32]  @108032
//  emb  float[128] @108160
//  fidx int[544]   @108672  .. 110848
#define SMEM_MAIN 110848
__global__ void k_main(const float* __restrict__ x, const float* __restrict__ emb,
                       const float* __restrict__ br, const float* __restrict__ bi) {
    extern __shared__ char smraw[];
    unsigned long long* tabc = (unsigned long long*)(smraw);
    unsigned long long* tabs = (unsigned long long*)(smraw + 16896);
    float*  y_re   = (float*) (smraw + 33792);
    float*  y_im   = (float*) (smraw + 50176);
    float*  ring   = (float*) (smraw + 66560);
    float2* cc     = (float2*)(smraw + 99328);
    float*  vs     = (float*) (smraw + 103680);
    float*  win_s  = (float*) (smraw + 107776);
    float*  ienv   = (float*) (smraw + 108032);
    float*  emb_s  = (float*) (smraw + 108160);
    int*    fidx_s = (int*)   (smraw + 108672);

    int tid = threadIdx.x;          // 256
    int blk = blockIdx.x;
    int b = blk >> 5, n = blk & 31;

    for (int i = tid; i < FB*NFFT; i += 256) {
        int f = i >> 6, t = i & 63;
        double ad = TWO_PI_D * (double)((f*t) & 63) / 64.0;
        float c = (float)cos(ad), s = (float)sin(ad);
        tabc[i] = pack2(c, c);
        tabs[i] = pack2(-s, -s);
    }
    for (int i = tid; i < NFFT; i += 256) {
        float a = TWO_PI * (float)i / (float)NFFT;
        win_s[i] = 0.5f - 0.5f * (float)cos((double)a);
    }
    for (int i = tid; i < HOPL; i += 256) {
        float a = TWO_PI * (float)i / (float)NFFT;
        float c = (float)cos((double)a);
        float w0 = 0.5f - 0.5f*c, w1 = 0.5f + 0.5f*c;
        ienv[i] = 1.0f / (w0*w0 + w1*w1);
    }
    for (int i = tid; i < ECH; i += 256) emb_s[i] = emb[i];
    for (int i = tid; i < WN*TOPM; i += 256) {
        cc[i]     = g_c[blk*WN*TOPM + i];
        fidx_s[i] = g_fidx[blk*WN*TOPM + i];
    }
    __syncthreads();

    int e0 = (tid & 31) << 2;       // e-fast across the warp
    int t0 = (tid >> 5) << 3;

    for (int w = 0; w < WN; w++) {
        for (int i = tid; i < 6*ECH; i += 256) {
            int k = i >> 7, e = i & 127;
            vs[i] = g_v[(k*WN + w)*ECH + e];
        }
        for (int i = tid; i < ECH; i += 256) {
            vs[6*ECH + i] = br[w*ECH + i];
            vs[7*ECH + i] = bi[w*ECH + i];
        }
        __syncthreads();

        // Y compute -> y_re/y_im indexed by rank m (scale folded, no scatter)
        for (int i = tid; i < ECH*TOPM; i += 256) {
            int m = i >> 7, e = i & 127;
            float2 c0 = cc[w*TOPM + m];
            float2 cl = (w > 0)    ? cc[(w-1)*TOPM + m] : make_float2(0.f,0.f);
            float2 cr = (w < WN-1) ? cc[(w+1)*TOPM + m] : make_float2(0.f,0.f);
            float vr  = vs[e],        vi  = vs[ECH+e];
            float vrl = vs[2*ECH+e],  vil = vs[3*ECH+e];
            float vrr = vs[4*ECH+e],  vir = vs[5*ECH+e];
            float ore = c0.x*vr - c0.y*vi + cl.x*vrl - cl.y*vil + cr.x*vrr - cr.y*vir + vs[6*ECH+e];
            float oim = c0.y*vr + c0.x*vi + cl.y*vrl + cl.x*vil + cr.y*vrr + cr.x*vir + vs[7*ECH+e];
            float yre = fmaxf(fmaxf(ore, 0.f) - LAMB, 0.f);
            float yim = fmaxf(fmaxf(oim, 0.f) - LAMB, 0.f);
            int f = fidx_s[w*TOPM + m];
            if (f == 0 || f == FB-1) {
                y_re[i] = yre * 0.015625f;   // 1/64, imag ignored by irfft
                y_im[i] = 0.f;
            } else {
                y_re[i] = yre * 0.03125f;    // 2/64
                y_im[i] = yim * 0.03125f;
            }
        }
        __syncthreads();

        // irfft directly over the 32 top-k bins, packed f32x2 accumulators
        unsigned long long acc2[2][8];
        #pragma unroll
        for (int p = 0; p < 2; p++)
            #pragma unroll
            for (int kk = 0; kk < 8; kk++) acc2[p][kk] = 0ull;

        for (int m = 0; m < TOPM; m++) {
            int f = fidx_s[w*TOPM + m];
            ulonglong2 yr = *(const ulonglong2*)&y_re[m*ECH + e0];
            ulonglong2 yi = *(const ulonglong2*)&y_im[m*ECH + e0];
            int fb = f*NFFT + t0;
            #pragma unroll
            for (int kk = 0; kk < 8; kk++) {
                unsigned long long c2 = tabc[fb + kk];   // broadcast
                unsigned long long s2 = tabs[fb + kk];
                fma2(acc2[0][kk], yr.x, c2);
                fma2(acc2[0][kk], yi.x, s2);
                fma2(acc2[1][kk], yr.y, c2);
                fma2(acc2[1][kk], yi.y, s2);
            }
        }

        #pragma unroll
        for (int kk = 0; kk < 8; kk++) {
            int t = t0 + kk;
            int slot = (w*HOPL + t) & 63;
            float wm = win_s[t];
            float4* rp = (float4*)&ring[slot*ECH + e0];
            float4 v;
            asm("mov.b64 {%0, %1}, %2;" : "=f"(v.x), "=f"(v.y) : "l"(acc2[0][kk]));
            asm("mov.b64 {%0, %1}, %2;" : "=f"(v.z), "=f"(v.w) : "l"(acc2[1][kk]));
            v.x *= wm; v.y *= wm; v.z *= wm; v.w *= wm;
            if (t < HOPL && w > 0) {
                float4 o = *rp;
                v.x += o.x; v.y += o.y; v.z += o.z; v.w += o.w;
            }
            *rp = v;
        }
        __syncthreads();

        if (w > 0) {
            for (int i = tid; i < HOPL*ECH; i += 256) {
                int r = i >> 7, e = i & 127;
                int t_out = (w-1)*HOPL + r;
                int slot = (w*HOPL + r) & 63;
                float val = ring[slot*ECH + e] * ienv[r]
                          + x[(b*SEQ + t_out)*NFch + n] * emb_s[e];
                g_xo[(size_t)blk*KTOT + t_out*ECH + e] = __uint_as_float(f2tf32u(val));
            }
        }
        __syncthreads();
    }
}

// ---------------- Kernel D: FC1 split-K, 1xTF32 tensor-core GEMM -----------
#define SA 36
#define SB 136
#define STAGE_A (128*SA)
#define STAGE_B (BK*SB)
#define STAGE_F (STAGE_A + STAGE_B)
#define SMEM_FC1 (2*STAGE_F*4)      // 71680 B
__global__ __launch_bounds__(256, 2) void k_fc1(const float* __restrict__ w1) {
    extern __shared__ float sm[];

    int m0 = blockIdx.x * 128, n0 = blockIdx.y * 128;
    int kbase = blockIdx.z * KCHUNK;
    int tid = threadIdx.x, lane = tid & 31, wid = tid >> 5;
    int wm = wid >> 1, wn = wid & 1;
    int ra = lane >> 2, ca = lane & 3;

    float acc[2][8][4];
    #pragma unroll
    for (int i = 0; i < 2; i++)
        #pragma unroll
        for (int j = 0; j < 8; j++)
            #pragma unroll
            for (int q = 0; q < 4; q++) acc[i][j][q] = 0.f;

    int am[4], ak[4], bk[4], bn[4];
    #pragma unroll
    for (int i = 0; i < 4; i++) {
        int c = tid + i*256;
        am[i] = c >> 3;  ak[i] = (c & 7) * 4;
        bk[i] = c >> 5;  bn[i] = (c & 31) * 4;
    }

    uint32_t smA[2], smB[2];
    smA[0] = smem_u32(sm);
    smB[0] = smA[0] + STAGE_A*4;
    smA[1] = smA[0] + STAGE_F*4;
    smB[1] = smB[0] + STAGE_F*4;

    {
        int kc = kbase;
        #pragma unroll
        for (int i = 0; i < 4; i++) {
            cp16(smA[0] + (am[i]*SA + ak[i])*4, &g_xo[(size_t)(m0+am[i])*KTOT + kc + ak[i]]);
            cp16(smB[0] + (bk[i]*SB + bn[i])*4, &w1[(size_t)(kc+bk[i])*HID + n0 + bn[i]]);
        }
        asm volatile("cp.async.commit_group;");
    }

    for (int it = 0; it < NSTAGE; it++) {
        if (it + 1 < NSTAGE) {
            int buf = (it+1) & 1;
            int kc = kbase + (it+1)*BK;
            #pragma unroll
            for (int i = 0; i < 4; i++) {
                cp16(smA[buf] + (am[i]*SA + ak[i])*4, &g_xo[(size_t)(m0+am[i])*KTOT + kc + ak[i]]);
                cp16(smB[buf] + (bk[i]*SB + bn[i])*4, &w1[(size_t)(kc+bk[i])*HID + n0 + bn[i]]);
            }
            asm volatile("cp.async.commit_group;");
            asm volatile("cp.async.wait_group 1;");
        } else {
            asm volatile("cp.async.wait_group 0;");
        }
        __syncthreads();

        const float* As = sm + (it & 1) * STAGE_F;
        const float* Bs = As + STAGE_A;

        #pragma unroll
        for (int ks = 0; ks < BK/8; ks++) {
            int k0 = ks*8 + ca;
            uint32_t ah[2][4];
            #pragma unroll
            for (int i = 0; i < 2; i++) {
                int mb = wm*32 + i*16;
                ah[i][0] = __float_as_uint(As[(mb+ra  )*SA + k0  ]);
                ah[i][1] = __float_as_uint(As[(mb+ra+8)*SA + k0  ]);
                ah[i][2] = __float_as_uint(As[(mb+ra  )*SA + k0+4]);
                ah[i][3] = __float_as_uint(As[(mb+ra+8)*SA + k0+4]);
            }
            #pragma unroll
            for (int j = 0; j < 8; j++) {
                int nb = wn*64 + j*8 + ra;
                uint32_t bh[2];
                bh[0] = f2tf32u(Bs[(k0  )*SB + nb]);
                bh[1] = f2tf32u(Bs[(k0+4)*SB + nb]);
                #pragma unroll
                for (int i = 0; i < 2; i++)
                    mma_tf32(acc[i][j], ah[i], bh);
            }
        }
        __syncthreads();
    }

    size_t base = (size_t)blockIdx.z * (ROWS*HID);
    #pragma unroll
    for (int i = 0; i < 2; i++) {
        #pragma unroll
        for (int j = 0; j < 8; j++) {
            int row = m0 + wm*32 + i*16 + ra;
            int col = n0 + wn*64 + j*8 + ca*2;
            *(float2*)&g_Hpart[base + (size_t)row*HID + col]     = make_float2(acc[i][j][0], acc[i][j][1]);
            *(float2*)&g_Hpart[base + (size_t)(row+8)*HID + col] = make_float2(acc[i][j][2], acc[i][j][3]);
        }
    }
}

__global__ void k_hred() {
    int i = blockIdx.x * 256 + threadIdx.x;
    if (i >= ROWS*HID) return;
    float s = 0.f;
    #pragma unroll
    for (int z = 0; z < KSPLIT; z++) s += g_Hpart[(size_t)z*(ROWS*HID) + i];
    g_H[i] = s;
}

// ---------------- Kernel E: leaky_relu + FC2 (exact fp32) + transpose ------
__global__ void k_fc2(const float* __restrict__ b1, const float* __restrict__ w2,
                      const float* __restrict__ b2, float* __restrict__ out) {
    __shared__ float hrow[HID];
    int row = blockIdx.x;
    int tid = threadIdx.x;          // 96
    for (int i = tid; i < HID; i += PRED) {
        float v = g_H[row*HID + i] + b1[i];
        hrow[i] = v > 0.f ? v : 0.01f * v;
    }
    __syncthreads();
    int b = row >> 5, n = row & 31;
    float acc = b2[tid];
    #pragma unroll 4
    for (int h = 0; h < HID; h++) acc = fmaf(hrow[h], w2[h*PRED + tid], acc);
    out[(b*PRED + tid)*NFch + n] = acc;
}

// ---------------------------------------------------------------------------
extern "C" void kernel_launch(void* const* d_in, const int* in_sizes, int n_in,
                              void* d_out, int out_size) {
    const float* x   = (const float*)d_in[0];
    const float* emb = (const float*)d_in[1];
    const float* br  = (const float*)d_in[8];
    const float* bi  = (const float*)d_in[9];
    const float* w1  = (const float*)d_in[10];
    const float* b1  = (const float*)d_in[11];
    const float* w2  = (const float*)d_in[12];
    const float* b2  = (const float*)d_in[13];
    float* out = (float*)d_out;

    cudaFuncSetAttribute(k_main, cudaFuncAttributeMaxDynamicSharedMemorySize, SMEM_MAIN);
    cudaFuncSetAttribute(k_fc1,  cudaFuncAttributeMaxDynamicSharedMemorySize, SMEM_FC1);

    k_stft<<<ROWS, 128>>>(x);
    k_vred<<<6*WN, 128>>>(emb, (const float*)d_in[2], (const float*)d_in[3],
                          (const float*)d_in[4], (const float*)d_in[5],
                          (const float*)d_in[6], (const float*)d_in[7]);
    k_main<<<ROWS, 256, SMEM_MAIN>>>(x, emb, br, bi);
    k_fc1<<<dim3(4, 4, KSPLIT), 256, SMEM_FC1>>>(w1);
    k_hred<<<(ROWS*HID + 255)/256, 256>>>();
    k_fc2<<<ROWS, PRED>>>(b1, w2, b2, out);
}

// round 9
// speedup vs baseline: 3.5722x; 1.1887x over previous
#include <cuda_runtime.h>
#include <math.h>
#include <stdint.h>

#define BQ    16
#define SEQ   512
#define NFch  32
#define ECH   128
#define HID   512
#define PRED  96
#define NFFT  64
#define HOPL  32
#define TOPM  32
#define WN    17
#define FB    33
#define LAMB  0.01f

#define ROWS  (BQ*NFch)      // 512  (b*32+n)
#define KTOT  (SEQ*ECH)      // 65536
#define KSPLIT 32
#define KCHUNK (KTOT/KSPLIT) // 2048
#define BK    32
#define NSTAGE (KCHUNK/BK)   // 64

// ---------------- scratch (static device globals; no runtime alloc) --------
__device__ float2 g_c[ROWS*WN*TOPM];
__device__ int    g_fidx[ROWS*WN*TOPM];
__device__ float  g_v[6*WN*ECH];
__device__ float  g_xo[(size_t)ROWS*KTOT];          // tf32-rounded, ~134MB
__device__ float  g_Hpart[(size_t)KSPLIT*ROWS*HID];
__device__ float  g_H[ROWS*HID];

#define TWO_PI 6.28318530717958647692f
#define TWO_PI_D 6.28318530717958647692528676655900577

__device__ __forceinline__ int reflect_t(int j) {
    int t = j - 32;
    if (t < 0) t = -t;
    else if (t > SEQ-1) t = 2*(SEQ-1) - t;
    return t;
}

__device__ __forceinline__ uint32_t f2tf32u(float f) {
    uint32_t r; asm("cvt.rna.tf32.f32 %0, %1;" : "=r"(r) : "f"(f)); return r;
}

__device__ __forceinline__ void mma_tf32(float* c, const uint32_t* a, const uint32_t* b) {
    asm volatile("mma.sync.aligned.m16n8k8.row.col.f32.tf32.tf32.f32 "
        "{%0,%1,%2,%3}, {%4,%5,%6,%7}, {%8,%9}, {%0,%1,%2,%3};"
        : "+f"(c[0]), "+f"(c[1]), "+f"(c[2]), "+f"(c[3])
        : "r"(a[0]), "r"(a[1]), "r"(a[2]), "r"(a[3]), "r"(b[0]), "r"(b[1]));
}

__device__ __forceinline__ uint32_t smem_u32(const void* p) {
    uint32_t a;
    asm("{ .reg .u64 t; cvta.to.shared.u64 t, %1; cvt.u32.u64 %0, t; }" : "=r"(a) : "l"(p));
    return a;
}
__device__ __forceinline__ void cp16(uint32_t dst, const void* src) {
    asm volatile("cp.async.ca.shared.global [%0], [%1], 16;" :: "r"(dst), "l"(src));
}

// packed f32x2 helpers (Blackwell FFMA2; IEEE fp32 per lane)
__device__ __forceinline__ void fma2(unsigned long long& acc, unsigned long long a, unsigned long long b) {
    asm("fma.rn.f32x2 %0, %1, %2, %0;" : "+l"(acc) : "l"(a), "l"(b));
}
__device__ __forceinline__ unsigned long long pack2(float lo, float hi) {
    unsigned long long r; asm("mov.b64 %0, {%1, %2};" : "=l"(r) : "f"(lo), "f"(hi)); return r;
}
__device__ __forceinline__ void unpack2(float& lo, float& hi, unsigned long long v) {
    asm("mov.b64 {%0, %1}, %2;" : "=f"(lo), "=f"(hi) : "l"(v));
}

// ---------------- Kernel A: STFT (df64 fp32, exact twiddles) + top-32 ------
__global__ void k_stft(const float* __restrict__ x) {
    __shared__ float s_s[SEQ];
    __shared__ float win_s[NFFT];
    __shared__ float chi_s[NFFT], clo_s[NFFT];
    __shared__ float mhi_s[NFFT], mlo_s[NFFT];
    __shared__ float Sre[WN*FB], Sim[WN*FB], Sab[WN*FB];
    int blk = blockIdx.x;
    int b = blk >> 5, n = blk & 31;
    int tid = threadIdx.x;          // 128

    for (int t = tid; t < SEQ; t += 128) s_s[t] = x[(b*SEQ + t)*NFch + n];
    for (int t = tid; t < NFFT; t += 128) {
        float a = TWO_PI * (float)t / (float)NFFT;
        win_s[t] = 0.5f - 0.5f * (float)cos((double)a);
        double ad = TWO_PI_D * (double)t / 64.0;
        double cd = cos(ad), msd = -sin(ad);
        float ch = (float)cd;  chi_s[t] = ch; clo_s[t] = (float)(cd - (double)ch);
        float mh = (float)msd; mhi_s[t] = mh; mlo_s[t] = (float)(msd - (double)mh);
    }
    __syncthreads();

    for (int task = tid; task < WN*FB; task += 128) {
        int w = task / FB, f = task % FB;
        float rh = 0.f, rl = 0.f, ih = 0.f, il = 0.f;
        for (int k = 0; k < NFFT; k++) {
            float v = s_s[reflect_t(w*HOPL + k)] * win_s[k];
            int a = (f*k) & 63;
            float ch = chi_s[a];
            float ph = v * ch;
            float pe = fmaf(v, ch, -ph);
            pe = fmaf(v, clo_s[a], pe);
            float s  = rh + ph;
            float bb = s - rh;
            float er = (rh - (s - bb)) + (ph - bb);
            rh = s; rl += er + pe;
            float mh = mhi_s[a];
            float qh = v * mh;
            float qe = fmaf(v, mh, -qh);
            qe = fmaf(v, mlo_s[a], qe);
            float s2  = ih + qh;
            float b2  = s2 - ih;
            float e2  = (ih - (s2 - b2)) + (qh - b2);
            ih = s2; il += e2 + qe;
        }
        float rf = rh + rl, imf = ih + il;
        Sre[task] = rf; Sim[task] = imf;
        Sab[task] = (float)sqrt((double)rf*rf + (double)imf*imf);
    }
    __syncthreads();

    if (tid < WN) {
        int w = tid;
        float mag[FB]; bool used[FB];
        for (int f = 0; f < FB; f++) { mag[f] = Sab[w*FB+f]; used[f] = false; }
        int base = (blk*WN + w) * TOPM;
        for (int m = 0; m < TOPM; m++) {
            int best = 0; float bv = -1.f;
            for (int f = 0; f < FB; f++)
                if (!used[f] && mag[f] > bv) { bv = mag[f]; best = f; }
            used[best] = true;
            g_fidx[base+m] = best;
            g_c[base+m] = make_float2(Sre[w*FB+best], Sim[w*FB+best]);
        }
    }
}

// ---------------- Kernel B: v[k][w][f] = sum_e emb[e]*Wk[w,e,f] ------------
__global__ void k_vred(const float* __restrict__ emb,
                       const float* __restrict__ Wr,  const float* __restrict__ Wi,
                       const float* __restrict__ Wrl, const float* __restrict__ Wil,
                       const float* __restrict__ Wrr, const float* __restrict__ Wir) {
    int k = blockIdx.x / WN, w = blockIdx.x % WN;
    const float* Wm = (k==0)?Wr:(k==1)?Wi:(k==2)?Wrl:(k==3)?Wil:(k==4)?Wrr:Wir;
    int f = threadIdx.x;
    const float* base = Wm + (size_t)w*ECH*ECH + f;
    float acc = 0.f;
    #pragma unroll 4
    for (int e = 0; e < ECH; e++) acc = fmaf(emb[e], base[(size_t)e*ECH], acc);
    g_v[(k*WN + w)*ECH + f] = acc;
}

// ---------------- Kernel C: fused Y + parity-paired irfft + OLA + bias -----
// t and t+32 share twiddles up to (-1)^f: accumulate even-f / odd-f sums,
// combine at the end. Twiddles packed (c,c,-s,-s) -> 1 LDS.128 per (bin,t).
// smem layout (bytes):
//  tab  ull2[FB*32] @0      .. 16896   {(c,c),(-s,-s)}
//  y_re float[4096] @16896  .. 33280
//  y_im float[4096] @33280  .. 49664
//  ring float[8192] @49664  .. 82432
//  cc   float2[544] @82432  .. 86784
//  vs   float[1024] @86784  .. 90880
//  win  float[64]   @90880
//  ienv float[32]   @91136
//  emb  float[128]  @91264
//  fidx int[544]    @91776  .. 93952
#define SMEM_MAIN 93952
__global__ void k_main(const float* __restrict__ x, const float* __restrict__ emb,
                       const float* __restrict__ br, const float* __restrict__ bi) {
    extern __shared__ char smraw[];
    ulonglong2* tab   = (ulonglong2*)(smraw);
    float*  y_re   = (float*) (smraw + 16896);
    float*  y_im   = (float*) (smraw + 33280);
    float*  ring   = (float*) (smraw + 49664);
    float2* cc     = (float2*)(smraw + 82432);
    float*  vs     = (float*) (smraw + 86784);
    float*  win_s  = (float*) (smraw + 90880);
    float*  ienv   = (float*) (smraw + 91136);
    float*  emb_s  = (float*) (smraw + 91264);
    int*    fidx_s = (int*)   (smraw + 91776);

    int tid = threadIdx.x;          // 256
    int blk = blockIdx.x;
    int b = blk >> 5, n = blk & 31;

    for (int i = tid; i < FB*32; i += 256) {
        int f = i >> 5, t = i & 31;
        double ad = TWO_PI_D * (double)((f*t) & 63) / 64.0;
        float c = (float)cos(ad), s = (float)sin(ad);
        ulonglong2 v; v.x = pack2(c, c); v.y = pack2(-s, -s);
        tab[i] = v;
    }
    for (int i = tid; i < NFFT; i += 256) {
        float a = TWO_PI * (float)i / (float)NFFT;
        win_s[i] = 0.5f - 0.5f * (float)cos((double)a);
    }
    for (int i = tid; i < HOPL; i += 256) {
        float a = TWO_PI * (float)i / (float)NFFT;
        float c = (float)cos((double)a);
        float w0 = 0.5f - 0.5f*c, w1 = 0.5f + 0.5f*c;
        ienv[i] = 1.0f / (w0*w0 + w1*w1);
    }
    for (int i = tid; i < ECH; i += 256) emb_s[i] = emb[i];
    for (int i = tid; i < WN*TOPM; i += 256) {
        cc[i]     = g_c[blk*WN*TOPM + i];
        fidx_s[i] = g_fidx[blk*WN*TOPM + i];
    }
    __syncthreads();

    int e0 = (tid & 31) << 2;       // 4 e per lane
    int t0 = (tid >> 5) << 2;       // 4 base t per warp (t in 0..31)

    for (int w = 0; w < WN; w++) {
        for (int i = tid; i < 6*ECH; i += 256) {
            int k = i >> 7, e = i & 127;
            vs[i] = g_v[(k*WN + w)*ECH + e];
        }
        for (int i = tid; i < ECH; i += 256) {
            vs[6*ECH + i] = br[w*ECH + i];
            vs[7*ECH + i] = bi[w*ECH + i];
        }
        __syncthreads();

        // Y compute -> y_re/y_im indexed by rank m (scale folded, no scatter)
        for (int i = tid; i < ECH*TOPM; i += 256) {
            int m = i >> 7, e = i & 127;
            float2 c0 = cc[w*TOPM + m];
            float2 cl = (w > 0)    ? cc[(w-1)*TOPM + m] : make_float2(0.f,0.f);
            float2 cr = (w < WN-1) ? cc[(w+1)*TOPM + m] : make_float2(0.f,0.f);
            float vr  = vs[e],        vi  = vs[ECH+e];
            float vrl = vs[2*ECH+e],  vil = vs[3*ECH+e];
            float vrr = vs[4*ECH+e],  vir = vs[5*ECH+e];
            float ore = c0.x*vr - c0.y*vi + cl.x*vrl - cl.y*vil + cr.x*vrr - cr.y*vir + vs[6*ECH+e];
            float oim = c0.y*vr + c0.x*vi + cl.y*vrl + cl.x*vil + cr.y*vrr + cr.x*vir + vs[7*ECH+e];
            float yre = fmaxf(fmaxf(ore, 0.f) - LAMB, 0.f);
            float yim = fmaxf(fmaxf(oim, 0.f) - LAMB, 0.f);
            int f = fidx_s[w*TOPM + m];
            if (f == 0 || f == FB-1) {
                y_re[i] = yre * 0.015625f;   // 1/64, imag ignored by irfft
                y_im[i] = 0.f;
            } else {
                y_re[i] = yre * 0.03125f;    // 2/64
                y_im[i] = yim * 0.03125f;
            }
        }
        __syncthreads();

        // irfft over 32 top-k bins with parity-split accumulators
        unsigned long long aE[2][4], aO[2][4];
        #pragma unroll
        for (int p = 0; p < 2; p++)
            #pragma unroll
            for (int kk = 0; kk < 4; kk++) { aE[p][kk] = 0ull; aO[p][kk] = 0ull; }

        #pragma unroll 4
        for (int m = 0; m < TOPM; m++) {
            int f = fidx_s[w*TOPM + m];                  // warp-uniform
            ulonglong2 yr = *(const ulonglong2*)&y_re[m*ECH + e0];
            ulonglong2 yi = *(const ulonglong2*)&y_im[m*ECH + e0];
            const ulonglong2* tw = tab + f*32 + t0;
            if (f & 1) {
                #pragma unroll
                for (int kk = 0; kk < 4; kk++) {
                    ulonglong2 cs = tw[kk];
                    fma2(aO[0][kk], yr.x, cs.x);
                    fma2(aO[0][kk], yi.x, cs.y);
                    fma2(aO[1][kk], yr.y, cs.x);
                    fma2(aO[1][kk], yi.y, cs.y);
                }
            } else {
                #pragma unroll
                for (int kk = 0; kk < 4; kk++) {
                    ulonglong2 cs = tw[kk];
                    fma2(aE[0][kk], yr.x, cs.x);
                    fma2(aE[0][kk], yi.x, cs.y);
                    fma2(aE[1][kk], yr.y, cs.x);
                    fma2(aE[1][kk], yi.y, cs.y);
                }
            }
        }

        // combine parities: out(t)=Pe+Po, out(t+32)=Pe-Po; window + ring OLA
        #pragma unroll
        for (int kk = 0; kk < 4; kk++) {
            int t  = t0 + kk;            // 0..31 : accumulates onto prev window
            int tm = t + 32;             // 32..63: fresh overwrite
            float pe0, pe1, pe2, pe3, po0, po1, po2, po3;
            unpack2(pe0, pe1, aE[0][kk]); unpack2(pe2, pe3, aE[1][kk]);
            unpack2(po0, po1, aO[0][kk]); unpack2(po2, po3, aO[1][kk]);

            float wt = win_s[t], wmr = win_s[tm];
            int slot_t  = (w*HOPL + t)  & 63;
            int slot_m  = (w*HOPL + tm) & 63;

            float4 vt, vm;
            vt.x = (pe0+po0)*wt; vt.y = (pe1+po1)*wt;
            vt.z = (pe2+po2)*wt; vt.w = (pe3+po3)*wt;
            vm.x = (pe0-po0)*wmr; vm.y = (pe1-po1)*wmr;
            vm.z = (pe2-po2)*wmr; vm.w = (pe3-po3)*wmr;

            float4* rpt = (float4*)&ring[slot_t*ECH + e0];
            if (w > 0) {
                float4 o = *rpt;
                vt.x += o.x; vt.y += o.y; vt.z += o.z; vt.w += o.w;
            }
            *rpt = vt;
            *(float4*)&ring[slot_m*ECH + e0] = vm;
        }
        __syncthreads();

        if (w > 0) {
            for (int i = tid; i < HOPL*ECH; i += 256) {
                int r = i >> 7, e = i & 127;
                int t_out = (w-1)*HOPL + r;
                int slot = (w*HOPL + r) & 63;
                float val = ring[slot*ECH + e] * ienv[r]
                          + x[(b*SEQ + t_out)*NFch + n] * emb_s[e];
                g_xo[(size_t)blk*KTOT + t_out*ECH + e] = __uint_as_float(f2tf32u(val));
            }
        }
        __syncthreads();
    }
}

// ---------------- Kernel D: FC1 split-K, 1xTF32 tensor-core GEMM -----------
#define SA 36
#define SB 136
#define STAGE_A (128*SA)
#define STAGE_B (BK*SB)
#define STAGE_F (STAGE_A + STAGE_B)
#define SMEM_FC1 (2*STAGE_F*4)      // 71680 B
__global__ __launch_bounds__(256, 2) void k_fc1(const float* __restrict__ w1) {
    extern __shared__ float sm[];

    int m0 = blockIdx.x * 128, n0 = blockIdx.y * 128;
    int kbase = blockIdx.z * KCHUNK;
    int tid = threadIdx.x, lane = tid & 31, wid = tid >> 5;
    int wm = wid >> 1, wn = wid & 1;
    int ra = lane >> 2, ca = lane & 3;

    float acc[2][8][4];
    #pragma unroll
    for (int i = 0; i < 2; i++)
        #pragma unroll
        for (int j = 0; j < 8; j++)
            #pragma unroll
            for (int q = 0; q < 4; q++) acc[i][j][q] = 0.f;

    int am[4], ak[4], bk[4], bn[4];
    #pragma unroll
    for (int i = 0; i < 4; i++) {
        int c = tid + i*256;
        am[i] = c >> 3;  ak[i] = (c & 7) * 4;
        bk[i] = c >> 5;  bn[i] = (c & 31) * 4;
    }

    uint32_t smA[2], smB[2];
    smA[0] = smem_u32(sm);
    smB[0] = smA[0] + STAGE_A*4;
    smA[1] = smA[0] + STAGE_F*4;
    smB[1] = smB[0] + STAGE_F*4;

    {
        int kc = kbase;
        #pragma unroll
        for (int i = 0; i < 4; i++) {
            cp16(smA[0] + (am[i]*SA + ak[i])*4, &g_xo[(size_t)(m0+am[i])*KTOT + kc + ak[i]]);
            cp16(smB[0] + (bk[i]*SB + bn[i])*4, &w1[(size_t)(kc+bk[i])*HID + n0 + bn[i]]);
        }
        asm volatile("cp.async.commit_group;");
    }

    for (int it = 0; it < NSTAGE; it++) {
        if (it + 1 < NSTAGE) {
            int buf = (it+1) & 1;
            int kc = kbase + (it+1)*BK;
            #pragma unroll
            for (int i = 0; i < 4; i++) {
                cp16(smA[buf] + (am[i]*SA + ak[i])*4, &g_xo[(size_t)(m0+am[i])*KTOT + kc + ak[i]]);
                cp16(smB[buf] + (bk[i]*SB + bn[i])*4, &w1[(size_t)(kc+bk[i])*HID + n0 + bn[i]]);
            }
            asm volatile("cp.async.commit_group;");
            asm volatile("cp.async.wait_group 1;");
        } else {
            asm volatile("cp.async.wait_group 0;");
        }
        __syncthreads();

        const float* As = sm + (it & 1) * STAGE_F;
        const float* Bs = As + STAGE_A;

        #pragma unroll
        for (int ks = 0; ks < BK/8; ks++) {
            int k0 = ks*8 + ca;
            uint32_t ah[2][4];
            #pragma unroll
            for (int i = 0; i < 2; i++) {
                int mb = wm*32 + i*16;
                ah[i][0] = __float_as_uint(As[(mb+ra  )*SA + k0  ]);
                ah[i][1] = __float_as_uint(As[(mb+ra+8)*SA + k0  ]);
                ah[i][2] = __float_as_uint(As[(mb+ra  )*SA + k0+4]);
                ah[i][3] = __float_as_uint(As[(mb+ra+8)*SA + k0+4]);
            }
            #pragma unroll
            for (int j = 0; j < 8; j++) {
                int nb = wn*64 + j*8 + ra;
                uint32_t bh[2];
                bh[0] = f2tf32u(Bs[(k0  )*SB + nb]);
                bh[1] = f2tf32u(Bs[(k0+4)*SB + nb]);
                #pragma unroll
                for (int i = 0; i < 2; i++)
                    mma_tf32(acc[i][j], ah[i], bh);
            }
        }
        __syncthreads();
    }

    size_t base = (size_t)blockIdx.z * (ROWS*HID);
    #pragma unroll
    for (int i = 0; i < 2; i++) {
        #pragma unroll
        for (int j = 0; j < 8; j++) {
            int row = m0 + wm*32 + i*16 + ra;
            int col = n0 + wn*64 + j*8 + ca*2;
            *(float2*)&g_Hpart[base + (size_t)row*HID + col]     = make_float2(acc[i][j][0], acc[i][j][1]);
            *(float2*)&g_Hpart[base + (size_t)(row+8)*HID + col] = make_float2(acc[i][j][2], acc[i][j][3]);
        }
    }
}

__global__ void k_hred() {
    int i = blockIdx.x * 256 + threadIdx.x;
    if (i >= ROWS*HID) return;
    float s = 0.f;
    #pragma unroll
    for (int z = 0; z < KSPLIT; z++) s += g_Hpart[(size_t)z*(ROWS*HID) + i];
    g_H[i] = s;
}

// ---------------- Kernel E: leaky_relu + FC2 (exact fp32) + transpose ------
__global__ void k_fc2(const float* __restrict__ b1, const float* __restrict__ w2,
                      const float* __restrict__ b2, float* __restrict__ out) {
    __shared__ float hrow[HID];
    int row = blockIdx.x;
    int tid = threadIdx.x;          // 96
    for (int i = tid; i < HID; i += PRED) {
        float v = g_H[row*HID + i] + b1[i];
        hrow[i] = v > 0.f ? v : 0.01f * v;
    }
    __syncthreads();
    int b = row >> 5, n = row & 31;
    float acc = b2[tid];
    #pragma unroll 4
    for (int h = 0; h < HID; h++) acc = fmaf(hrow[h], w2[h*PRED + tid], acc);
    out[(b*PRED + tid)*NFch + n] = acc;
}

// ---------------------------------------------------------------------------
extern "C" void kernel_launch(void* const* d_in, const int* in_sizes, int n_in,
                              void* d_out, int out_size) {
    const float* x   = (const float*)d_in[0];
    const float* emb = (const float*)d_in[1];
    const float* br  = (const float*)d_in[8];
    const float* bi  = (const float*)d_in[9];
    const float* w1  = (const float*)d_in[10];
    const float* b1  = (const float*)d_in[11];
    const float* w2  = (const float*)d_in[12];
    const float* b2  = (const float*)d_in[13];
    float* out = (float*)d_out;

    cudaFuncSetAttribute(k_main, cudaFuncAttributeMaxDynamicSharedMemorySize, SMEM_MAIN);
    cudaFuncSetAttribute(k_fc1,  cudaFuncAttributeMaxDynamicSharedMemorySize, SMEM_FC1);

    k_stft<<<ROWS, 128>>>(x);
    k_vred<<<6*WN, 128>>>(emb, (const float*)d_in[2], (const float*)d_in[3],
                          (const float*)d_in[4], (const float*)d_in[5],
                          (const float*)d_in[6], (const float*)d_in[7]);
    k_main<<<ROWS, 256, SMEM_MAIN>>>(x, emb, br, bi);
    k_fc1<<<dim3(4, 4, KSPLIT), 256, SMEM_FC1>>>(w1);
    k_hred<<<(ROWS*HID + 255)/256, 256>>>();
    k_fc2<<<ROWS, PRED>>>(b1, w2, b2, out);
}

// round 10
// speedup vs baseline: 3.8567x; 1.0796x over previous
#include <cuda_runtime.h>
#include <math.h>
#include <stdint.h>

#define BQ    16
#define SEQ   512
#define NFch  32
#define ECH   128
#define HID   512
#define PRED  96
#define NFFT  64
#define HOPL  32
#define TOPM  32
#define WN    17
#define FB    33
#define LAMB  0.01f

#define ROWS  (BQ*NFch)      // 512  (b*32+n)
#define KTOT  (SEQ*ECH)      // 65536
#define KSPLIT 32
#define KCHUNK (KTOT/KSPLIT) // 2048
#define BK    32
#define NSTAGE (KCHUNK/BK)   // 64
#define EH    64             // e-channels per k_main CTA (e-split)

// ---------------- scratch (static device globals; no runtime alloc) --------
__device__ float2 g_c[ROWS*WN*TOPM];
__device__ int    g_fidx[ROWS*WN*TOPM];
__device__ float  g_v[6*WN*ECH];
__device__ float  g_xo[(size_t)ROWS*KTOT];          // tf32-rounded, ~134MB
__device__ float  g_Hpart[(size_t)KSPLIT*ROWS*HID];
__device__ float  g_H[ROWS*HID];

#define TWO_PI 6.28318530717958647692f
#define TWO_PI_D 6.28318530717958647692528676655900577

__device__ __forceinline__ int reflect_t(int j) {
    int t = j - 32;
    if (t < 0) t = -t;
    else if (t > SEQ-1) t = 2*(SEQ-1) - t;
    return t;
}

__device__ __forceinline__ uint32_t f2tf32u(float f) {
    uint32_t r; asm("cvt.rna.tf32.f32 %0, %1;" : "=r"(r) : "f"(f)); return r;
}

__device__ __forceinline__ void mma_tf32(float* c, const uint32_t* a, const uint32_t* b) {
    asm volatile("mma.sync.aligned.m16n8k8.row.col.f32.tf32.tf32.f32 "
        "{%0,%1,%2,%3}, {%4,%5,%6,%7}, {%8,%9}, {%0,%1,%2,%3};"
        : "+f"(c[0]), "+f"(c[1]), "+f"(c[2]), "+f"(c[3])
        : "r"(a[0]), "r"(a[1]), "r"(a[2]), "r"(a[3]), "r"(b[0]), "r"(b[1]));
}

__device__ __forceinline__ uint32_t smem_u32(const void* p) {
    uint32_t a;
    asm("{ .reg .u64 t; cvta.to.shared.u64 t, %1; cvt.u32.u64 %0, t; }" : "=r"(a) : "l"(p));
    return a;
}
__device__ __forceinline__ void cp16(uint32_t dst, const void* src) {
    asm volatile("cp.async.ca.shared.global [%0], [%1], 16;" :: "r"(dst), "l"(src));
}

// packed f32x2 helpers (Blackwell FFMA2; IEEE fp32 per lane)
__device__ __forceinline__ void fma2(unsigned long long& acc, unsigned long long a, unsigned long long b) {
    asm("fma.rn.f32x2 %0, %1, %2, %0;" : "+l"(acc) : "l"(a), "l"(b));
}
__device__ __forceinline__ unsigned long long pack2(float lo, float hi) {
    unsigned long long r; asm("mov.b64 %0, {%1, %2};" : "=l"(r) : "f"(lo), "f"(hi)); return r;
}
__device__ __forceinline__ void unpack2(float& lo, float& hi, unsigned long long v) {
    asm("mov.b64 {%0, %1}, %2;" : "=f"(lo), "=f"(hi) : "l"(v));
}

// ---------------- Kernel A: STFT (df64 fp32, exact twiddles) + top-32 ------
__global__ void k_stft(const float* __restrict__ x) {
    __shared__ float s_s[SEQ];
    __shared__ float win_s[NFFT];
    __shared__ float chi_s[NFFT], clo_s[NFFT];
    __shared__ float mhi_s[NFFT], mlo_s[NFFT];
    __shared__ float Sre[WN*FB], Sim[WN*FB], Sab[WN*FB];
    int blk = blockIdx.x;
    int b = blk >> 5, n = blk & 31;
    int tid = threadIdx.x;          // 128

    for (int t = tid; t < SEQ; t += 128) s_s[t] = x[(b*SEQ + t)*NFch + n];
    for (int t = tid; t < NFFT; t += 128) {
        float a = TWO_PI * (float)t / (float)NFFT;
        win_s[t] = 0.5f - 0.5f * (float)cos((double)a);
        double ad = TWO_PI_D * (double)t / 64.0;
        double cd = cos(ad), msd = -sin(ad);
        float ch = (float)cd;  chi_s[t] = ch; clo_s[t] = (float)(cd - (double)ch);
        float mh = (float)msd; mhi_s[t] = mh; mlo_s[t] = (float)(msd - (double)mh);
    }
    __syncthreads();

    for (int task = tid; task < WN*FB; task += 128) {
        int w = task / FB, f = task % FB;
        float rh = 0.f, rl = 0.f, ih = 0.f, il = 0.f;
        for (int k = 0; k < NFFT; k++) {
            float v = s_s[reflect_t(w*HOPL + k)] * win_s[k];
            int a = (f*k) & 63;
            float ch = chi_s[a];
            float ph = v * ch;
            float pe = fmaf(v, ch, -ph);
            pe = fmaf(v, clo_s[a], pe);
            float s  = rh + ph;
            float bb = s - rh;
            float er = (rh - (s - bb)) + (ph - bb);
            rh = s; rl += er + pe;
            float mh = mhi_s[a];
            float qh = v * mh;
            float qe = fmaf(v, mh, -qh);
            qe = fmaf(v, mlo_s[a], qe);
            float s2  = ih + qh;
            float b2  = s2 - ih;
            float e2  = (ih - (s2 - b2)) + (qh - b2);
            ih = s2; il += e2 + qe;
        }
        float rf = rh + rl, imf = ih + il;
        Sre[task] = rf; Sim[task] = imf;
        Sab[task] = (float)sqrt((double)rf*rf + (double)imf*imf);
    }
    __syncthreads();

    if (tid < WN) {
        int w = tid;
        float mag[FB]; bool used[FB];
        for (int f = 0; f < FB; f++) { mag[f] = Sab[w*FB+f]; used[f] = false; }
        int base = (blk*WN + w) * TOPM;
        for (int m = 0; m < TOPM; m++) {
            int best = 0; float bv = -1.f;
            for (int f = 0; f < FB; f++)
                if (!used[f] && mag[f] > bv) { bv = mag[f]; best = f; }
            used[best] = true;
            g_fidx[base+m] = best;
            g_c[base+m] = make_float2(Sre[w*FB+best], Sim[w*FB+best]);
        }
    }
}

// ---------------- Kernel B: v[k][w][f] = sum_e emb[e]*Wk[w,e,f] ------------
__global__ void k_vred(const float* __restrict__ emb,
                       const float* __restrict__ Wr,  const float* __restrict__ Wi,
                       const float* __restrict__ Wrl, const float* __restrict__ Wil,
                       const float* __restrict__ Wrr, const float* __restrict__ Wir) {
    int k = blockIdx.x / WN, w = blockIdx.x % WN;
    const float* Wm = (k==0)?Wr:(k==1)?Wi:(k==2)?Wrl:(k==3)?Wil:(k==4)?Wrr:Wir;
    int f = threadIdx.x;
    const float* base = Wm + (size_t)w*ECH*ECH + f;
    float acc = 0.f;
    #pragma unroll 4
    for (int e = 0; e < ECH; e++) acc = fmaf(emb[e], base[(size_t)e*ECH], acc);
    g_v[(k*WN + w)*ECH + f] = acc;
}

// ---------------- Kernel C: e-split fused Y + parity irfft + OLA + bias ----
// grid = ROWS*2; CTA handles 64 e-channels (half). Compact 64-entry twiddle
// table indexed by (f*t)&63. 43KB smem -> 4 CTAs/SM.
// smem layout (bytes):
//  tw64 ull2[64]     @0     .. 1024
//  y_re float[2048]  @1024  .. 9216
//  y_im float[2048]  @9216  .. 17408
//  ring float[4096]  @17408 .. 33792
//  cc   float2[544]  @33792 .. 38144
//  vs   float[512]   @38144 .. 40192
//  win  float[64]    @40192 .. 40448
//  ienv float[32]    @40448 .. 40576
//  emb  float[64]    @40576 .. 40832
//  fidx int[544]     @40832 .. 43008
#define SMEM_MAIN 43008
__global__ __launch_bounds__(256, 4) void k_main(
        const float* __restrict__ x, const float* __restrict__ emb,
        const float* __restrict__ br, const float* __restrict__ bi) {
    extern __shared__ char smraw[];
    ulonglong2* tw64 = (ulonglong2*)(smraw);
    float*  y_re   = (float*) (smraw + 1024);
    float*  y_im   = (float*) (smraw + 9216);
    float*  ring   = (float*) (smraw + 17408);
    float2* cc     = (float2*)(smraw + 33792);
    float*  vs     = (float*) (smraw + 38144);
    float*  win_s  = (float*) (smraw + 40192);
    float*  ienv   = (float*) (smraw + 40448);
    float*  emb_s  = (float*) (smraw + 40576);
    int*    fidx_s = (int*)   (smraw + 40832);

    int tid = threadIdx.x;          // 256
    int bx  = blockIdx.x;           // (b*32+n)*2 + half
    int blk = bx >> 1, half = bx & 1;
    int e_off = half * EH;
    int b = blk >> 5, n = blk & 31;

    for (int i = tid; i < 64; i += 256) {
        double ad = TWO_PI_D * (double)i / 64.0;
        float c = (float)cos(ad), s = (float)sin(ad);
        ulonglong2 v; v.x = pack2(c, c); v.y = pack2(-s, -s);
        tw64[i] = v;
    }
    for (int i = tid; i < NFFT; i += 256) {
        float a = TWO_PI * (float)i / (float)NFFT;
        win_s[i] = 0.5f - 0.5f * (float)cos((double)a);
    }
    for (int i = tid; i < HOPL; i += 256) {
        float a = TWO_PI * (float)i / (float)NFFT;
        float c = (float)cos((double)a);
        float w0 = 0.5f - 0.5f*c, w1 = 0.5f + 0.5f*c;
        ienv[i] = 1.0f / (w0*w0 + w1*w1);
    }
    for (int i = tid; i < EH; i += 256) emb_s[i] = emb[e_off + i];
    for (int i = tid; i < WN*TOPM; i += 256) {
        cc[i]     = g_c[blk*WN*TOPM + i];
        fidx_s[i] = g_fidx[blk*WN*TOPM + i];
    }
    __syncthreads();

    int lane = tid & 31, wid = tid >> 5;
    int e0l = (lane & 15) << 2;                 // local e 0..60 (quad)
    int t0  = wid*4 + ((lane >> 4) << 1);       // base t 0..30 (pair)

    for (int w = 0; w < WN; w++) {
        for (int i = tid; i < 8*EH; i += 256) {
            int k = i >> 6, e = i & 63;
            float v;
            if (k < 6)      v = g_v[(k*WN + w)*ECH + e_off + e];
            else if (k == 6) v = br[w*ECH + e_off + e];
            else             v = bi[w*ECH + e_off + e];
            vs[i] = v;
        }
        __syncthreads();

        // Y compute for this e-half, indexed by rank m (scale folded)
        for (int i = tid; i < EH*TOPM; i += 256) {
            int m = i >> 6, e = i & 63;
            float2 c0 = cc[w*TOPM + m];
            float2 cl = (w > 0)    ? cc[(w-1)*TOPM + m] : make_float2(0.f,0.f);
            float2 cr = (w < WN-1) ? cc[(w+1)*TOPM + m] : make_float2(0.f,0.f);
            float vr  = vs[e],       vi  = vs[EH+e];
            float vrl = vs[2*EH+e],  vil = vs[3*EH+e];
            float vrr = vs[4*EH+e],  vir = vs[5*EH+e];
            float ore = c0.x*vr - c0.y*vi + cl.x*vrl - cl.y*vil + cr.x*vrr - cr.y*vir + vs[6*EH+e];
            float oim = c0.y*vr + c0.x*vi + cl.y*vrl + cl.x*vil + cr.y*vrr + cr.x*vir + vs[7*EH+e];
            float yre = fmaxf(fmaxf(ore, 0.f) - LAMB, 0.f);
            float yim = fmaxf(fmaxf(oim, 0.f) - LAMB, 0.f);
            int f = fidx_s[w*TOPM + m];
            if (f == 0 || f == FB-1) {
                y_re[i] = yre * 0.015625f;   // 1/64, imag ignored by irfft
                y_im[i] = 0.f;
            } else {
                y_re[i] = yre * 0.03125f;    // 2/64
                y_im[i] = yim * 0.03125f;
            }
        }
        __syncthreads();

        // irfft over 32 top-k bins, parity-split accumulators, compact table
        unsigned long long aE[2][2], aO[2][2];   // [kk][e-pair]
        #pragma unroll
        for (int kk = 0; kk < 2; kk++) {
            aE[kk][0] = aE[kk][1] = 0ull;
            aO[kk][0] = aO[kk][1] = 0ull;
        }

        #pragma unroll 4
        for (int m = 0; m < TOPM; m++) {
            int f = fidx_s[w*TOPM + m];                  // warp-uniform
            ulonglong2 yr = *(const ulonglong2*)&y_re[m*EH + e0l];
            ulonglong2 yi = *(const ulonglong2*)&y_im[m*EH + e0l];
            int ft = f * t0;
            ulonglong2 cs0 = tw64[ft & 63];
            ulonglong2 cs1 = tw64[(ft + f) & 63];
            if (f & 1) {
                fma2(aO[0][0], yr.x, cs0.x); fma2(aO[0][0], yi.x, cs0.y);
                fma2(aO[0][1], yr.y, cs0.x); fma2(aO[0][1], yi.y, cs0.y);
                fma2(aO[1][0], yr.x, cs1.x); fma2(aO[1][0], yi.x, cs1.y);
                fma2(aO[1][1], yr.y, cs1.x); fma2(aO[1][1], yi.y, cs1.y);
            } else {
                fma2(aE[0][0], yr.x, cs0.x); fma2(aE[0][0], yi.x, cs0.y);
                fma2(aE[0][1], yr.y, cs0.x); fma2(aE[0][1], yi.y, cs0.y);
                fma2(aE[1][0], yr.x, cs1.x); fma2(aE[1][0], yi.x, cs1.y);
                fma2(aE[1][1], yr.y, cs1.x); fma2(aE[1][1], yi.y, cs1.y);
            }
        }

        // combine parities: out(t)=Pe+Po, out(t+32)=Pe-Po; window + ring OLA
        #pragma unroll
        for (int kk = 0; kk < 2; kk++) {
            int t  = t0 + kk;            // 0..31 : accumulates onto prev window
            int tm = t + 32;             // 32..63: fresh overwrite
            float pe0, pe1, pe2, pe3, po0, po1, po2, po3;
            unpack2(pe0, pe1, aE[kk][0]); unpack2(pe2, pe3, aE[kk][1]);
            unpack2(po0, po1, aO[kk][0]); unpack2(po2, po3, aO[kk][1]);

            float wt = win_s[t], wmr = win_s[tm];
            int slot_t = (w*HOPL + t)  & 63;
            int slot_m = (w*HOPL + tm) & 63;

            float4 vt, vm;
            vt.x = (pe0+po0)*wt;  vt.y = (pe1+po1)*wt;
            vt.z = (pe2+po2)*wt;  vt.w = (pe3+po3)*wt;
            vm.x = (pe0-po0)*wmr; vm.y = (pe1-po1)*wmr;
            vm.z = (pe2-po2)*wmr; vm.w = (pe3-po3)*wmr;

            float4* rpt = (float4*)&ring[slot_t*EH + e0l];
            if (w > 0) {
                float4 o = *rpt;
                vt.x += o.x; vt.y += o.y; vt.z += o.z; vt.w += o.w;
            }
            *rpt = vt;
            *(float4*)&ring[slot_m*EH + e0l] = vm;
        }
        __syncthreads();

        if (w > 0) {
            for (int i = tid; i < HOPL*EH; i += 256) {
                int r = i >> 6, e = i & 63;
                int t_out = (w-1)*HOPL + r;
                int slot = (w*HOPL + r) & 63;
                float val = ring[slot*EH + e] * ienv[r]
                          + x[(b*SEQ + t_out)*NFch + n] * emb_s[e];
                g_xo[(size_t)blk*KTOT + t_out*ECH + e_off + e] = __uint_as_float(f2tf32u(val));
            }
        }
        __syncthreads();
    }
}

// ---------------- Kernel D: FC1 split-K, 1xTF32 tensor-core GEMM -----------
#define SA 36
#define SB 136
#define STAGE_A (128*SA)
#define STAGE_B (BK*SB)
#define STAGE_F (STAGE_A + STAGE_B)
#define SMEM_FC1 (2*STAGE_F*4)      // 71680 B
__global__ __launch_bounds__(256, 2) void k_fc1(const float* __restrict__ w1) {
    extern __shared__ float sm[];

    int m0 = blockIdx.x * 128, n0 = blockIdx.y * 128;
    int kbase = blockIdx.z * KCHUNK;
    int tid = threadIdx.x, lane = tid & 31, wid = tid >> 5;
    int wm = wid >> 1, wn = wid & 1;
    int ra = lane >> 2, ca = lane & 3;

    float acc[2][8][4];
    #pragma unroll
    for (int i = 0; i < 2; i++)
        #pragma unroll
        for (int j = 0; j < 8; j++)
            #pragma unroll
            for (int q = 0; q < 4; q++) acc[i][j][q] = 0.f;

    int am[4], ak[4], bk[4], bn[4];
    #pragma unroll
    for (int i = 0; i < 4; i++) {
        int c = tid + i*256;
        am[i] = c >> 3;  ak[i] = (c & 7) * 4;
        bk[i] = c >> 5;  bn[i] = (c & 31) * 4;
    }

    uint32_t smA[2], smB[2];
    smA[0] = smem_u32(sm);
    smB[0] = smA[0] + STAGE_A*4;
    smA[1] = smA[0] + STAGE_F*4;
    smB[1] = smB[0] + STAGE_F*4;

    {
        int kc = kbase;
        #pragma unroll
        for (int i = 0; i < 4; i++) {
            cp16(smA[0] + (am[i]*SA + ak[i])*4, &g_xo[(size_t)(m0+am[i])*KTOT + kc + ak[i]]);
            cp16(smB[0] + (bk[i]*SB + bn[i])*4, &w1[(size_t)(kc+bk[i])*HID + n0 + bn[i]]);
        }
        asm volatile("cp.async.commit_group;");
    }

    for (int it = 0; it < NSTAGE; it++) {
        if (it + 1 < NSTAGE) {
            int buf = (it+1) & 1;
            int kc = kbase + (it+1)*BK;
            #pragma unroll
            for (int i = 0; i < 4; i++) {
                cp16(smA[buf] + (am[i]*SA + ak[i])*4, &g_xo[(size_t)(m0+am[i])*KTOT + kc + ak[i]]);
                cp16(smB[buf] + (bk[i]*SB + bn[i])*4, &w1[(size_t)(kc+bk[i])*HID + n0 + bn[i]]);
            }
            asm volatile("cp.async.commit_group;");
            asm volatile("cp.async.wait_group 1;");
        } else {
            asm volatile("cp.async.wait_group 0;");
        }
        __syncthreads();

        const float* As = sm + (it & 1) * STAGE_F;
        const float* Bs = As + STAGE_A;

        #pragma unroll
        for (int ks = 0; ks < BK/8; ks++) {
            int k0 = ks*8 + ca;
            uint32_t ah[2][4];
            #pragma unroll
            for (int i = 0; i < 2; i++) {
                int mb = wm*32 + i*16;
                ah[i][0] = __float_as_uint(As[(mb+ra  )*SA + k0  ]);
                ah[i][1] = __float_as_uint(As[(mb+ra+8)*SA + k0  ]);
                ah[i][2] = __float_as_uint(As[(mb+ra  )*SA + k0+4]);
                ah[i][3] = __float_as_uint(As[(mb+ra+8)*SA + k0+4]);
            }
            #pragma unroll
            for (int j = 0; j < 8; j++) {
                int nb = wn*64 + j*8 + ra;
                uint32_t bh[2];
                bh[0] = f2tf32u(Bs[(k0  )*SB + nb]);
                bh[1] = f2tf32u(Bs[(k0+4)*SB + nb]);
                #pragma unroll
                for (int i = 0; i < 2; i++)
                    mma_tf32(acc[i][j], ah[i], bh);
            }
        }
        __syncthreads();
    }

    size_t base = (size_t)blockIdx.z * (ROWS*HID);
    #pragma unroll
    for (int i = 0; i < 2; i++) {
        #pragma unroll
        for (int j = 0; j < 8; j++) {
            int row = m0 + wm*32 + i*16 + ra;
            int col = n0 + wn*64 + j*8 + ca*2;
            *(float2*)&g_Hpart[base + (size_t)row*HID + col]     = make_float2(acc[i][j][0], acc[i][j][1]);
            *(float2*)&g_Hpart[base + (size_t)(row+8)*HID + col] = make_float2(acc[i][j][2], acc[i][j][3]);
        }
    }
}

__global__ void k_hred() {
    int i = blockIdx.x * 256 + threadIdx.x;
    if (i >= ROWS*HID) return;
    float s = 0.f;
    #pragma unroll
    for (int z = 0; z < KSPLIT; z++) s += g_Hpart[(size_t)z*(ROWS*HID) + i];
    g_H[i] = s;
}

// ---------------- Kernel E: leaky_relu + FC2 (exact fp32) + transpose ------
__global__ void k_fc2(const float* __restrict__ b1, const float* __restrict__ w2,
                      const float* __restrict__ b2, float* __restrict__ out) {
    __shared__ float hrow[HID];
    int row = blockIdx.x;
    int tid = threadIdx.x;          // 96
    for (int i = tid; i < HID; i += PRED) {
        float v = g_H[row*HID + i] + b1[i];
        hrow[i] = v > 0.f ? v : 0.01f * v;
    }
    __syncthreads();
    int b = row >> 5, n = row & 31;
    float acc = b2[tid];
    #pragma unroll 4
    for (int h = 0; h < HID; h++) acc = fmaf(hrow[h], w2[h*PRED + tid], acc);
    out[(b*PRED + tid)*NFch + n] = acc;
}

// ---------------------------------------------------------------------------
extern "C" void kernel_launch(void* const* d_in, const int* in_sizes, int n_in,
                              void* d_out, int out_size) {
    const float* x   = (const float*)d_in[0];
    const float* emb = (const float*)d_in[1];
    const float* br  = (const float*)d_in[8];
    const float* bi  = (const float*)d_in[9];
    const float* w1  = (const float*)d_in[10];
    const float* b1  = (const float*)d_in[11];
    const float* w2  = (const float*)d_in[12];
    const float* b2  = (const float*)d_in[13];
    float* out = (float*)d_out;

    cudaFuncSetAttribute(k_main, cudaFuncAttributeMaxDynamicSharedMemorySize, SMEM_MAIN);
    cudaFuncSetAttribute(k_fc1,  cudaFuncAttributeMaxDynamicSharedMemorySize, SMEM_FC1);

    k_stft<<<ROWS, 128>>>(x);
    k_vred<<<6*WN, 128>>>(emb, (const float*)d_in[2], (const float*)d_in[3],
                          (const float*)d_in[4], (const float*)d_in[5],
                          (const float*)d_in[6], (const float*)d_in[7]);
    k_main<<<ROWS*2, 256, SMEM_MAIN>>>(x, emb, br, bi);
    k_fc1<<<dim3(4, 4, KSPLIT), 256, SMEM_FC1>>>(w1);
    k_hred<<<(ROWS*HID + 255)/256, 256>>>();
    k_fc2<<<ROWS, PRED>>>(b1, w2, b2, out);
}